// round 1
// baseline (speedup 1.0000x reference)
#include <cuda_runtime.h>
#include <cuda_bf16.h>
#include <cstdint>

#define BB 8
#define CC 256
#define HH_ 96
#define WW_ 96
#define NP_FULL 9216   // 96*96
#define GP 576         // 24*24
#define HGD 24
#define SCALE 0.17677669529663688f   // 32^-0.5

// ---------------- static scratch ----------------
__device__ float g_low[(size_t)BB*CC*GP];
__device__ float g_high[(size_t)BB*CC*NP_FULL];
__device__ float g_dw[(size_t)BB*CC*NP_FULL];     // reused for all dw outputs
__device__ float g_lq[(size_t)BB*128*NP_FULL];
__device__ float g_lkvdw[(size_t)BB*CC*GP];
__device__ float g_lkv[(size_t)BB*CC*GP];
__device__ float g_lattn[(size_t)BB*128*NP_FULL];
__device__ float g_qkv[(size_t)BB*384*NP_FULL];
__device__ float g_ho[(size_t)BB*128*NP_FULL];

// ---------------- kernel 1: 4x4 avg pool ----------------
__global__ void pool_k(const float* __restrict__ x, float* __restrict__ low) {
    int i = blockIdx.x * blockDim.x + threadIdx.x;
    if (i >= BB*CC*GP) return;
    int g = i % GP; int bc = i / GP;
    int gy = g / HGD, gx = g % HGD;
    const float* xp = x + (size_t)bc*NP_FULL + (gy*4)*WW_ + gx*4;
    float s = 0.f;
#pragma unroll
    for (int r = 0; r < 4; r++) {
        float4 v = *(const float4*)(xp + r*WW_);
        s += (v.x + v.y) + (v.z + v.w);
    }
    low[i] = s * (1.0f/16.0f);
}

// ---------------- kernel 2: high = restore(pixelshuffle(low)) - x ----------------
__global__ void high_k(const float* __restrict__ x, const float* __restrict__ low,
                       const float* __restrict__ rw, const float* __restrict__ rb,
                       float* __restrict__ high) {
    __shared__ float ws[256*16];
    __shared__ float bs[256];
    int tid = threadIdx.x;
    for (int i = tid; i < 256*16; i += 256) ws[i] = rw[i];
    bs[tid] = rb[tid];
    __syncthreads();
    int b = blockIdx.y;
    int p = blockIdx.x * 256 + tid;
    int h = p / WW_, w = p % WW_;
    int off = (h & 3)*4 + (w & 3);
    int g = (h >> 2)*HGD + (w >> 2);
    float lv[16];
#pragma unroll
    for (int ci = 0; ci < 16; ci++)
        lv[ci] = low[((size_t)b*CC + ci*16 + off)*GP + g];
    const float* xp = x + (size_t)b*CC*NP_FULL + p;
    float* hp = high + (size_t)b*CC*NP_FULL + p;
    for (int oc = 0; oc < 256; oc++) {
        float s = bs[oc];
#pragma unroll
        for (int ci = 0; ci < 16; ci++) s += ws[oc*16+ci]*lv[ci];
        hp[(size_t)oc*NP_FULL] = s - xp[(size_t)oc*NP_FULL];
    }
}

// ---------------- kernel 3: generic depthwise 3x3, pad 1 ----------------
__global__ void dw_k(const float* __restrict__ in, const float* __restrict__ w,
                     const float* __restrict__ bias, float* __restrict__ out,
                     int Ctot, int Hd, int Wd, int total) {
    int i = blockIdx.x * blockDim.x + threadIdx.x;
    if (i >= total) return;
    int xw = i % Wd; int t = i / Wd; int y = t % Hd; t /= Hd; int c = t % Ctot;
    int hw = Hd * Wd;
    const float* ip = in + (size_t)(i / hw) * hw;
    const float* wp = w + c*9;
    float acc = bias[c];
#pragma unroll
    for (int dy = -1; dy <= 1; dy++) {
        int yy = y + dy; if (yy < 0 || yy >= Hd) continue;
#pragma unroll
        for (int dx = -1; dx <= 1; dx++) {
            int xx = xw + dx; if (xx < 0 || xx >= Wd) continue;
            acc += wp[(dy+1)*3 + (dx+1)] * ip[yy*Wd + xx];
        }
    }
    out[i] = acc;
}

// ---------------- kernel 4: pointwise 1x1 conv as tiled GEMM ----------------
// tile: 64 OC x 128 P, TK=16, 256 threads, 4x8 microtile
__global__ __launch_bounds__(256) void pw_k(
    const float* __restrict__ in, const float* __restrict__ wgt,
    const float* __restrict__ bias, float* __restrict__ out,
    int IC, int NP, int out_cstride, int out_coff) {
    __shared__ float As[16][64];
    __shared__ float Bs[16][128];
    int b = blockIdx.z;
    int oc0 = blockIdx.y * 64;
    int p0 = blockIdx.x * 128;
    int tid = threadIdx.x;
    const float* inb = in + (size_t)b * IC * NP;
    float acc[4][8];
#pragma unroll
    for (int i = 0; i < 4; i++)
#pragma unroll
        for (int j = 0; j < 8; j++) acc[i][j] = 0.f;
    int ty = tid >> 4, tx = tid & 15;
    int a_oc = tid >> 2;
    int a_k0 = (tid & 3) * 4;
    int b_k  = tid >> 4;
    int b_p0 = (tid & 15) * 8;

    for (int k0 = 0; k0 < IC; k0 += 16) {
        float4 av = *(const float4*)(wgt + (size_t)(oc0 + a_oc)*IC + k0 + a_k0);
        As[a_k0+0][a_oc] = av.x; As[a_k0+1][a_oc] = av.y;
        As[a_k0+2][a_oc] = av.z; As[a_k0+3][a_oc] = av.w;
        int pg = p0 + b_p0;
        const float* brow = inb + (size_t)(k0 + b_k)*NP;
        if (pg + 7 < NP) {
            float4 b0 = *(const float4*)(brow + pg);
            float4 b1 = *(const float4*)(brow + pg + 4);
            Bs[b_k][b_p0+0] = b0.x; Bs[b_k][b_p0+1] = b0.y;
            Bs[b_k][b_p0+2] = b0.z; Bs[b_k][b_p0+3] = b0.w;
            Bs[b_k][b_p0+4] = b1.x; Bs[b_k][b_p0+5] = b1.y;
            Bs[b_k][b_p0+6] = b1.z; Bs[b_k][b_p0+7] = b1.w;
        } else {
#pragma unroll
            for (int j = 0; j < 8; j++)
                Bs[b_k][b_p0+j] = (pg + j < NP) ? brow[pg + j] : 0.f;
        }
        __syncthreads();
#pragma unroll
        for (int kk = 0; kk < 16; kk++) {
            float4 a = *(const float4*)&As[kk][ty*4];
            float4 v0 = *(const float4*)&Bs[kk][tx*8];
            float4 v1 = *(const float4*)&Bs[kk][tx*8+4];
            float bv[8] = {v0.x, v0.y, v0.z, v0.w, v1.x, v1.y, v1.z, v1.w};
            float aa[4] = {a.x, a.y, a.z, a.w};
#pragma unroll
            for (int i = 0; i < 4; i++)
#pragma unroll
                for (int j = 0; j < 8; j++)
                    acc[i][j] = fmaf(aa[i], bv[j], acc[i][j]);
        }
        __syncthreads();
    }
    float* ob = out + (size_t)b * out_cstride * NP;
#pragma unroll
    for (int i = 0; i < 4; i++) {
        int oc = oc0 + ty*4 + i;
        float bv = bias[oc];
        float* orow = ob + (size_t)(out_coff + oc) * NP;
#pragma unroll
        for (int j = 0; j < 8; j++) {
            int pp = p0 + tx*8 + j;
            if (pp < NP) orow[pp] = acc[i][j] + bv;
        }
    }
}

// ---------------- kernel 7: low-frequency global attention ----------------
// K,V (576x32 each) in smem; 1 q-row per thread, online softmax
__global__ __launch_bounds__(256) void lattn_k(
    const float* __restrict__ q, const float* __restrict__ kv,
    float* __restrict__ o) {
    extern __shared__ float sm[];
    float* Ks = sm;
    float* Vs = sm + GP*32;
    int b = blockIdx.z, h = blockIdx.y;
    int p = blockIdx.x * 256 + threadIdx.x;
    const float* kvb = kv + ((size_t)b*256 + h*32)*GP;
    for (int i = threadIdx.x; i < GP*32; i += 256) {
        int d = i / GP, kp = i - d*GP;
        Ks[kp*32 + d] = kvb[(size_t)d*GP + kp];
        Vs[kp*32 + d] = kvb[(size_t)(128 + d)*GP + kp];
    }
    __syncthreads();
    float qv[32];
    const float* qb = q + ((size_t)b*128 + h*32)*NP_FULL + p;
#pragma unroll
    for (int d = 0; d < 32; d++) qv[d] = qb[(size_t)d*NP_FULL];
    float m = -1e30f, l = 0.f;
    float O[32];
#pragma unroll
    for (int d = 0; d < 32; d++) O[d] = 0.f;

    for (int kp = 0; kp < GP; kp++) {
        const float4* k4 = (const float4*)(Ks + kp*32);
        float s0 = 0.f, s1 = 0.f, s2 = 0.f, s3 = 0.f;
#pragma unroll
        for (int ii = 0; ii < 8; ii++) {
            float4 kk = k4[ii];
            s0 = fmaf(qv[ii*4+0], kk.x, s0);
            s1 = fmaf(qv[ii*4+1], kk.y, s1);
            s2 = fmaf(qv[ii*4+2], kk.z, s2);
            s3 = fmaf(qv[ii*4+3], kk.w, s3);
        }
        float s = ((s0 + s1) + (s2 + s3)) * SCALE;
        const float4* v4 = (const float4*)(Vs + kp*32);
        if (s <= m) {
            float pe = __expf(s - m);
            l += pe;
#pragma unroll
            for (int ii = 0; ii < 8; ii++) {
                float4 vv = v4[ii];
                O[ii*4+0] = fmaf(pe, vv.x, O[ii*4+0]);
                O[ii*4+1] = fmaf(pe, vv.y, O[ii*4+1]);
                O[ii*4+2] = fmaf(pe, vv.z, O[ii*4+2]);
                O[ii*4+3] = fmaf(pe, vv.w, O[ii*4+3]);
            }
        } else {
            float al = __expf(m - s);
            l = fmaf(l, al, 1.f);
            m = s;
#pragma unroll
            for (int ii = 0; ii < 8; ii++) {
                float4 vv = v4[ii];
                O[ii*4+0] = fmaf(O[ii*4+0], al, vv.x);
                O[ii*4+1] = fmaf(O[ii*4+1], al, vv.y);
                O[ii*4+2] = fmaf(O[ii*4+2], al, vv.z);
                O[ii*4+3] = fmaf(O[ii*4+3], al, vv.w);
            }
        }
    }
    float inv = 1.f / l;
    float* ob = o + ((size_t)b*128 + h*32)*NP_FULL + p;
#pragma unroll
    for (int d = 0; d < 32; d++) ob[(size_t)d*NP_FULL] = O[d] * inv;
}

// ---------------- kernel 12: high-frequency windowed attention ----------------
// 4 windows x 4 heads x 16 tokens per 256-thread block; qkv tile in smem
__global__ __launch_bounds__(256) void hattn_k(
    const float* __restrict__ qkv, float* __restrict__ ho) {
    extern __shared__ float sm[];   // [384][64]
    int b = blockIdx.y;
    int g0 = blockIdx.x * 4;
    const float* qb = qkv + (size_t)b*384*NP_FULL;
    for (int i = threadIdx.x; i < 384*64; i += 256) {
        int c = i >> 6; int px = i & 63;
        int win = px >> 4, t = px & 15;
        int g = g0 + win; int gy = g / HGD, gx = g - gy*HGD;
        int pp = (gy*4 + (t >> 2))*WW_ + gx*4 + (t & 3);
        sm[i] = qb[(size_t)c*NP_FULL + pp];
    }
    __syncthreads();
    int tid = threadIdx.x;
    int t = tid & 15; int n = (tid >> 4) & 3; int win = tid >> 6;
    int pxb = win*16;
    float qv[32];
#pragma unroll
    for (int d = 0; d < 32; d++) qv[d] = sm[(n*32 + d)*64 + pxb + t];
    float sc[16];
    float mx = -1e30f;
#pragma unroll
    for (int k = 0; k < 16; k++) {
        float s = 0.f;
#pragma unroll
        for (int d = 0; d < 32; d++)
            s = fmaf(qv[d], sm[((4 + n)*32 + d)*64 + pxb + k], s);
        s *= SCALE;
        sc[k] = s;
        mx = fmaxf(mx, s);
    }
    float l = 0.f;
#pragma unroll
    for (int k = 0; k < 16; k++) { sc[k] = __expf(sc[k] - mx); l += sc[k]; }
    float inv = 1.f / l;
    int g = g0 + win; int gy = g / HGD, gx = g - gy*HGD;
    int pp = (gy*4 + (t >> 2))*WW_ + gx*4 + (t & 3);
    float* ob = ho + (size_t)b*128*NP_FULL + pp;
#pragma unroll
    for (int d = 0; d < 32; d++) {
        float s = 0.f;
#pragma unroll
        for (int k = 0; k < 16; k++)
            s = fmaf(sc[k], sm[((8 + n)*32 + d)*64 + pxb + k], s);
        ob[(size_t)(n*32 + d)*NP_FULL] = s * inv;
    }
}

// ---------------- launch ----------------
extern "C" void kernel_launch(void* const* d_in, const int* in_sizes, int n_in,
                              void* d_out, int out_size) {
    const float* x          = (const float*)d_in[0];
    const float* restore_w  = (const float*)d_in[1];
    const float* restore_b  = (const float*)d_in[2];
    const float* lq_dw_w    = (const float*)d_in[3];
    const float* lq_dw_b    = (const float*)d_in[4];
    const float* lq_pw_w    = (const float*)d_in[5];
    const float* lq_pw_b    = (const float*)d_in[6];
    const float* lkv_dw_w   = (const float*)d_in[7];
    const float* lkv_dw_b   = (const float*)d_in[8];
    const float* lkv_pw_w   = (const float*)d_in[9];
    const float* lkv_pw_b   = (const float*)d_in[10];
    const float* lproj_dw_w = (const float*)d_in[11];
    const float* lproj_dw_b = (const float*)d_in[12];
    const float* lproj_pw_w = (const float*)d_in[13];
    const float* lproj_pw_b = (const float*)d_in[14];
    const float* hqkv_dw_w  = (const float*)d_in[15];
    const float* hqkv_dw_b  = (const float*)d_in[16];
    const float* hqkv_pw_w  = (const float*)d_in[17];
    const float* hqkv_pw_b  = (const float*)d_in[18];
    const float* hproj_dw_w = (const float*)d_in[19];
    const float* hproj_dw_b = (const float*)d_in[20];
    const float* hproj_pw_w = (const float*)d_in[21];
    const float* hproj_pw_b = (const float*)d_in[22];
    float* out = (float*)d_out;

    float *low, *high, *dwb, *lq, *lkvdw, *lkv, *lattn, *qkvb, *ho;
    cudaGetSymbolAddress((void**)&low,   g_low);
    cudaGetSymbolAddress((void**)&high,  g_high);
    cudaGetSymbolAddress((void**)&dwb,   g_dw);
    cudaGetSymbolAddress((void**)&lq,    g_lq);
    cudaGetSymbolAddress((void**)&lkvdw, g_lkvdw);
    cudaGetSymbolAddress((void**)&lkv,   g_lkv);
    cudaGetSymbolAddress((void**)&lattn, g_lattn);
    cudaGetSymbolAddress((void**)&qkvb,  g_qkv);
    cudaGetSymbolAddress((void**)&ho,    g_ho);

    static bool attr_done = false;
    if (!attr_done) {
        cudaFuncSetAttribute(lattn_k, cudaFuncAttributeMaxDynamicSharedMemorySize, 2*GP*32*sizeof(float));
        cudaFuncSetAttribute(hattn_k, cudaFuncAttributeMaxDynamicSharedMemorySize, 384*64*sizeof(float));
        attr_done = true;
    }

    // 1. pool
    {
        int total = BB*CC*GP;
        pool_k<<<(total + 255)/256, 256>>>(x, low);
    }
    // 2. high = restore(PS(low)) - x
    high_k<<<dim3(NP_FULL/256, BB), 256>>>(x, low, restore_w, restore_b, high);
    // 3. lq depthwise on x
    {
        int total = BB*CC*NP_FULL;
        dw_k<<<(total + 255)/256, 256>>>(x, lq_dw_w, lq_dw_b, dwb, CC, HH_, WW_, total);
    }
    // 4. lq pointwise 256->128
    pw_k<<<dim3(NP_FULL/128, 128/64, BB), 256>>>(dwb, lq_pw_w, lq_pw_b, lq, 256, NP_FULL, 128, 0);
    // 5. lkv depthwise on low (24x24)
    {
        int total = BB*CC*GP;
        dw_k<<<(total + 255)/256, 256>>>(low, lkv_dw_w, lkv_dw_b, lkvdw, CC, HGD, HGD, total);
    }
    // 6. lkv pointwise 256->256
    pw_k<<<dim3((GP + 127)/128, 256/64, BB), 256>>>(lkvdw, lkv_pw_w, lkv_pw_b, lkv, 256, GP, 256, 0);
    // 7. low attention
    lattn_k<<<dim3(NP_FULL/256, 4, BB), 256, 2*GP*32*sizeof(float)>>>(lq, lkv, lattn);
    // 8. lproj depthwise
    {
        int total = BB*128*NP_FULL;
        dw_k<<<(total + 255)/256, 256>>>(lattn, lproj_dw_w, lproj_dw_b, dwb, 128, HH_, WW_, total);
    }
    // 9. lproj pointwise 128->128 -> out channels [0,128)
    pw_k<<<dim3(NP_FULL/128, 128/64, BB), 256>>>(dwb, lproj_pw_w, lproj_pw_b, out, 128, NP_FULL, 256, 0);
    // 10. hqkv depthwise on high
    {
        int total = BB*CC*NP_FULL;
        dw_k<<<(total + 255)/256, 256>>>(high, hqkv_dw_w, hqkv_dw_b, dwb, CC, HH_, WW_, total);
    }
    // 11. hqkv pointwise 256->384
    pw_k<<<dim3(NP_FULL/128, 384/64, BB), 256>>>(dwb, hqkv_pw_w, hqkv_pw_b, qkvb, 256, NP_FULL, 384, 0);
    // 12. high windowed attention
    hattn_k<<<dim3(GP/4, BB), 256, 384*64*sizeof(float)>>>(qkvb, ho);
    // 13. hproj depthwise
    {
        int total = BB*128*NP_FULL;
        dw_k<<<(total + 255)/256, 256>>>(ho, hproj_dw_w, hproj_dw_b, dwb, 128, HH_, WW_, total);
    }
    // 14. hproj pointwise 128->128 -> out channels [128,256)
    pw_k<<<dim3(NP_FULL/128, 128/64, BB), 256>>>(dwb, hproj_pw_w, hproj_pw_b, out, 128, NP_FULL, 256, 128);
}

// round 2
// speedup vs baseline: 1.4437x; 1.4437x over previous
#include <cuda_runtime.h>
#include <cuda_bf16.h>
#include <cstdint>

#define BB 8
#define CC 256
#define HH_ 96
#define WW_ 96
#define NP_FULL 9216   // 96*96
#define GP 576         // 24*24
#define HGD 24
#define SCALE 0.17677669529663688f   // 32^-0.5

typedef unsigned long long ull;

__device__ __forceinline__ ull pack2(float x, float y) {
    ull r;
    asm("mov.b64 %0, {%1, %2};" : "=l"(r) : "f"(x), "f"(y));
    return r;
}
__device__ __forceinline__ void unpack2(ull v, float& x, float& y) {
    asm("mov.b64 {%0, %1}, %2;" : "=f"(x), "=f"(y) : "l"(v));
}
__device__ __forceinline__ ull fma2(ull a, ull b, ull c) {
    ull d;
    asm("fma.rn.f32x2 %0, %1, %2, %3;" : "=l"(d) : "l"(a), "l"(b), "l"(c));
    return d;
}
__device__ __forceinline__ ull add2(ull a, ull b) {
    ull d;
    asm("add.rn.f32x2 %0, %1, %2;" : "=l"(d) : "l"(a), "l"(b));
    return d;
}

// ---------------- static scratch ----------------
__device__ float g_low[(size_t)BB*CC*GP];
__device__ float g_high[(size_t)BB*CC*NP_FULL];
__device__ float g_dw[(size_t)BB*CC*NP_FULL];     // reused for all dw outputs
__device__ float g_lq[(size_t)BB*128*NP_FULL];
__device__ float g_lkvdw[(size_t)BB*CC*GP];
__device__ float g_lkv[(size_t)BB*CC*GP];
__device__ float g_lattn[(size_t)BB*128*NP_FULL];
__device__ float g_qkv[(size_t)BB*384*NP_FULL];
__device__ float g_ho[(size_t)BB*128*NP_FULL];

// ---------------- kernel 1: 4x4 avg pool ----------------
__global__ void pool_k(const float* __restrict__ x, float* __restrict__ low) {
    int i = blockIdx.x * blockDim.x + threadIdx.x;
    if (i >= BB*CC*GP) return;
    int g = i % GP; int bc = i / GP;
    int gy = g / HGD, gx = g % HGD;
    const float* xp = x + (size_t)bc*NP_FULL + (gy*4)*WW_ + gx*4;
    float s = 0.f;
#pragma unroll
    for (int r = 0; r < 4; r++) {
        float4 v = *(const float4*)(xp + r*WW_);
        s += (v.x + v.y) + (v.z + v.w);
    }
    low[i] = s * (1.0f/16.0f);
}

// ---------------- kernel 2: high = restore(pixelshuffle(low)) - x ----------------
__global__ void high_k(const float* __restrict__ x, const float* __restrict__ low,
                       const float* __restrict__ rw, const float* __restrict__ rb,
                       float* __restrict__ high) {
    __shared__ float ws[256*16];
    __shared__ float bs[256];
    int tid = threadIdx.x;
    for (int i = tid; i < 256*16; i += 256) ws[i] = rw[i];
    bs[tid] = rb[tid];
    __syncthreads();
    int b = blockIdx.y;
    int p = blockIdx.x * 256 + tid;
    int h = p / WW_, w = p % WW_;
    int off = (h & 3)*4 + (w & 3);
    int g = (h >> 2)*HGD + (w >> 2);
    ull lv2[8];
#pragma unroll
    for (int ci = 0; ci < 8; ci++) {
        float a = low[((size_t)b*CC + (2*ci+0)*16 + off)*GP + g];
        float bb2 = low[((size_t)b*CC + (2*ci+1)*16 + off)*GP + g];
        lv2[ci] = pack2(a, bb2);
    }
    const float* xp = x + (size_t)b*CC*NP_FULL + p;
    float* hp = high + (size_t)b*CC*NP_FULL + p;
    for (int oc = 0; oc < 256; oc++) {
        const ull* wrow = (const ull*)&ws[oc*16];
        ull acc = 0ull;
#pragma unroll
        for (int ci = 0; ci < 8; ci++) acc = fma2(lv2[ci], wrow[ci], acc);
        float sx, sy; unpack2(acc, sx, sy);
        float s = bs[oc] + sx + sy;
        hp[(size_t)oc*NP_FULL] = s - xp[(size_t)oc*NP_FULL];
    }
}

// ---------------- kernel 3: depthwise 3x3 pad1, 4 outputs per thread ----------------
__global__ void dw_k(const float* __restrict__ in, const float* __restrict__ w,
                     const float* __restrict__ bias, float* __restrict__ out,
                     int Ctot, int Hd, int Wd, int total4) {
    int i = blockIdx.x * blockDim.x + threadIdx.x;
    if (i >= total4) return;
    int wq = Wd >> 2;
    int xq = i % wq; int t = i / wq;
    int y = t % Hd;
    int bcimg = t / Hd;
    int c = bcimg % Ctot;
    int x0 = xq * 4;
    const float* ip = in + (size_t)bcimg * Hd * Wd;
    const float* wp = w + c*9;
    float wv[9];
#pragma unroll
    for (int k = 0; k < 9; k++) wv[k] = __ldg(wp + k);

    float r[3][6];
#pragma unroll
    for (int rr = 0; rr < 3; rr++) {
        int yy = y + rr - 1;
        bool yok = (yy >= 0) && (yy < Hd);
        const float* row = ip + yy*Wd;
        if (yok) {
            float4 mid = *(const float4*)(row + x0);
            r[rr][1] = mid.x; r[rr][2] = mid.y; r[rr][3] = mid.z; r[rr][4] = mid.w;
            r[rr][0] = (x0 > 0) ? row[x0-1] : 0.f;
            r[rr][5] = (x0 + 4 < Wd) ? row[x0+4] : 0.f;
        } else {
#pragma unroll
            for (int j = 0; j < 6; j++) r[rr][j] = 0.f;
        }
    }
    float bvv = bias[c];
    float a0 = bvv, a1 = bvv, a2 = bvv, a3 = bvv;
#pragma unroll
    for (int rr = 0; rr < 3; rr++) {
#pragma unroll
        for (int dx = 0; dx < 3; dx++) {
            float wc = wv[rr*3 + dx];
            a0 = fmaf(wc, r[rr][0+dx], a0);
            a1 = fmaf(wc, r[rr][1+dx], a1);
            a2 = fmaf(wc, r[rr][2+dx], a2);
            a3 = fmaf(wc, r[rr][3+dx], a3);
        }
    }
    float4 o; o.x = a0; o.y = a1; o.z = a2; o.w = a3;
    *(float4*)(out + (size_t)bcimg*Hd*Wd + y*Wd + x0) = o;
}

// ---------------- kernel 4: pointwise 1x1 conv as tiled GEMM (f32x2) ----------------
// tile: 128 OC x 128 P, BK=16, 256 threads, 8x8 microtile via FFMA2
__global__ __launch_bounds__(256) void pw_k(
    const float* __restrict__ in, const float* __restrict__ wgt,
    const float* __restrict__ bias, float* __restrict__ out,
    int IC, int NP, int out_cstride, int out_coff) {
    __shared__ float As[16][132];
    __shared__ float Bs[16][132];
    int b = blockIdx.z;
    int oc0 = blockIdx.y * 128;
    int p0 = blockIdx.x * 128;
    int tid = threadIdx.x;
    int ty = tid >> 4, tx = tid & 15;
    const float* inb = in + (size_t)b * IC * NP;

    int a_oc = tid >> 1;
    int a_k0 = (tid & 1) * 8;
    int b_k  = tid >> 4;
    int b_p  = (tid & 15) * 8;

    ull acc[8][4];
#pragma unroll
    for (int i = 0; i < 8; i++)
#pragma unroll
        for (int j = 0; j < 4; j++) acc[i][j] = 0ull;

    for (int k0 = 0; k0 < IC; k0 += 16) {
        // A: weights [OC][IC] -> As[k][oc]
        const float* wr = wgt + (size_t)(oc0 + a_oc)*IC + k0 + a_k0;
        float4 w0 = *(const float4*)(wr);
        float4 w1 = *(const float4*)(wr + 4);
        As[a_k0+0][a_oc] = w0.x; As[a_k0+1][a_oc] = w0.y;
        As[a_k0+2][a_oc] = w0.z; As[a_k0+3][a_oc] = w0.w;
        As[a_k0+4][a_oc] = w1.x; As[a_k0+5][a_oc] = w1.y;
        As[a_k0+6][a_oc] = w1.z; As[a_k0+7][a_oc] = w1.w;
        // B: input [IC][NP] -> Bs[k][p]
        int pg = p0 + b_p;
        const float* brow = inb + (size_t)(k0 + b_k)*NP;
        if (pg + 7 < NP) {
            float4 b0 = *(const float4*)(brow + pg);
            float4 b1 = *(const float4*)(brow + pg + 4);
            *(float4*)&Bs[b_k][b_p]   = b0;
            *(float4*)&Bs[b_k][b_p+4] = b1;
        } else {
#pragma unroll
            for (int j = 0; j < 8; j++)
                Bs[b_k][b_p+j] = (pg + j < NP) ? brow[pg + j] : 0.f;
        }
        __syncthreads();
#pragma unroll
        for (int kk = 0; kk < 16; kk++) {
            float4 a0 = *(const float4*)&As[kk][ty*8];
            float4 a1 = *(const float4*)&As[kk][ty*8+4];
            float4 b0 = *(const float4*)&Bs[kk][tx*8];
            float4 b1 = *(const float4*)&Bs[kk][tx*8+4];
            ull bp[4];
            bp[0] = pack2(b0.x, b0.y); bp[1] = pack2(b0.z, b0.w);
            bp[2] = pack2(b1.x, b1.y); bp[3] = pack2(b1.z, b1.w);
            float aa[8] = {a0.x, a0.y, a0.z, a0.w, a1.x, a1.y, a1.z, a1.w};
#pragma unroll
            for (int i = 0; i < 8; i++) {
                ull ad = pack2(aa[i], aa[i]);
#pragma unroll
                for (int j = 0; j < 4; j++)
                    acc[i][j] = fma2(ad, bp[j], acc[i][j]);
            }
        }
        __syncthreads();
    }
    float* ob = out + (size_t)b * out_cstride * NP + (size_t)out_coff * NP;
    int pp = p0 + tx*8;
#pragma unroll
    for (int i = 0; i < 8; i++) {
        int oc = oc0 + ty*8 + i;
        float bv = __ldg(bias + oc);
        float v[8];
        unpack2(acc[i][0], v[0], v[1]);
        unpack2(acc[i][1], v[2], v[3]);
        unpack2(acc[i][2], v[4], v[5]);
        unpack2(acc[i][3], v[6], v[7]);
#pragma unroll
        for (int j = 0; j < 8; j++) v[j] += bv;
        float* orow = ob + (size_t)oc * NP;
        if (pp + 7 < NP) {
            float4 s0; s0.x=v[0]; s0.y=v[1]; s0.z=v[2]; s0.w=v[3];
            float4 s1; s1.x=v[4]; s1.y=v[5]; s1.z=v[6]; s1.w=v[7];
            *(float4*)(orow + pp) = s0;
            *(float4*)(orow + pp + 4) = s1;
        } else {
#pragma unroll
            for (int j = 0; j < 8; j++)
                if (pp + j < NP) orow[pp + j] = v[j];
        }
    }
}

// ---------------- kernel 7: low-frequency global attention (f32x2) ----------------
__global__ __launch_bounds__(256) void lattn_k(
    const float* __restrict__ q, const float* __restrict__ kv,
    float* __restrict__ o) {
    extern __shared__ float sm[];
    float* Ks = sm;
    float* Vs = sm + GP*32;
    int b = blockIdx.z, h = blockIdx.y;
    int p = blockIdx.x * 256 + threadIdx.x;
    const float* kvb = kv + ((size_t)b*256 + h*32)*GP;
    for (int i = threadIdx.x; i < GP*32; i += 256) {
        int d = i / GP, kp = i - d*GP;
        Ks[kp*32 + d] = kvb[(size_t)d*GP + kp];
        Vs[kp*32 + d] = kvb[(size_t)(128 + d)*GP + kp];
    }
    __syncthreads();
    ull q2[16];
    const float* qb = q + ((size_t)b*128 + h*32)*NP_FULL + p;
#pragma unroll
    for (int d = 0; d < 16; d++) {
        float x0 = qb[(size_t)(2*d+0)*NP_FULL];
        float x1 = qb[(size_t)(2*d+1)*NP_FULL];
        q2[d] = pack2(x0, x1);
    }
    float m = -1e30f, l = 0.f;
    ull O2[16];
#pragma unroll
    for (int d = 0; d < 16; d++) O2[d] = 0ull;

    for (int kp = 0; kp < GP; kp++) {
        const ulonglong2* k2 = (const ulonglong2*)(Ks + kp*32);
        ull a0 = 0ull, a1 = 0ull, a2 = 0ull, a3 = 0ull;
#pragma unroll
        for (int ii = 0; ii < 4; ii++) {
            ulonglong2 u0 = k2[ii*2];
            ulonglong2 u1 = k2[ii*2+1];
            a0 = fma2(q2[ii*4+0], u0.x, a0);
            a1 = fma2(q2[ii*4+1], u0.y, a1);
            a2 = fma2(q2[ii*4+2], u1.x, a2);
            a3 = fma2(q2[ii*4+3], u1.y, a3);
        }
        ull t01 = add2(a0, a1);
        ull t23 = add2(a2, a3);
        ull tt = add2(t01, t23);
        float sx, sy; unpack2(tt, sx, sy);
        float s = (sx + sy) * SCALE;
        const ulonglong2* v2 = (const ulonglong2*)(Vs + kp*32);
        if (s <= m) {
            float pe = __expf(s - m);
            l += pe;
            ull pe2 = pack2(pe, pe);
#pragma unroll
            for (int ii = 0; ii < 8; ii++) {
                ulonglong2 vv = v2[ii];
                O2[ii*2+0] = fma2(pe2, vv.x, O2[ii*2+0]);
                O2[ii*2+1] = fma2(pe2, vv.y, O2[ii*2+1]);
            }
        } else {
            float al = __expf(m - s);
            l = fmaf(l, al, 1.f);
            m = s;
            ull al2 = pack2(al, al);
#pragma unroll
            for (int ii = 0; ii < 8; ii++) {
                ulonglong2 vv = v2[ii];
                O2[ii*2+0] = fma2(O2[ii*2+0], al2, vv.x);
                O2[ii*2+1] = fma2(O2[ii*2+1], al2, vv.y);
            }
        }
    }
    float inv = 1.f / l;
    float* ob = o + ((size_t)b*128 + h*32)*NP_FULL + p;
#pragma unroll
    for (int d = 0; d < 16; d++) {
        float x0, x1; unpack2(O2[d], x0, x1);
        ob[(size_t)(2*d+0)*NP_FULL] = x0 * inv;
        ob[(size_t)(2*d+1)*NP_FULL] = x1 * inv;
    }
}

// ---------------- kernel 12: high-frequency windowed attention ----------------
__global__ __launch_bounds__(256) void hattn_k(
    const float* __restrict__ qkv, float* __restrict__ ho) {
    extern __shared__ float sm[];   // [384][64]
    int b = blockIdx.y;
    int g0 = blockIdx.x * 4;
    const float* qb = qkv + (size_t)b*384*NP_FULL;
    for (int i = threadIdx.x; i < 384*64; i += 256) {
        int c = i >> 6; int px = i & 63;
        int win = px >> 4, t = px & 15;
        int g = g0 + win; int gy = g / HGD, gx = g - gy*HGD;
        int pp = (gy*4 + (t >> 2))*WW_ + gx*4 + (t & 3);
        sm[i] = qb[(size_t)c*NP_FULL + pp];
    }
    __syncthreads();
    int tid = threadIdx.x;
    int t = tid & 15; int n = (tid >> 4) & 3; int win = tid >> 6;
    int pxb = win*16;
    float qv[32];
#pragma unroll
    for (int d = 0; d < 32; d++) qv[d] = sm[(n*32 + d)*64 + pxb + t];
    float sc[16];
    float mx = -1e30f;
#pragma unroll
    for (int k = 0; k < 16; k++) {
        float s = 0.f;
#pragma unroll
        for (int d = 0; d < 32; d++)
            s = fmaf(qv[d], sm[((4 + n)*32 + d)*64 + pxb + k], s);
        s *= SCALE;
        sc[k] = s;
        mx = fmaxf(mx, s);
    }
    float l = 0.f;
#pragma unroll
    for (int k = 0; k < 16; k++) { sc[k] = __expf(sc[k] - mx); l += sc[k]; }
    float inv = 1.f / l;
    int g = g0 + win; int gy = g / HGD, gx = g - gy*HGD;
    int pp = (gy*4 + (t >> 2))*WW_ + gx*4 + (t & 3);
    float* ob = ho + (size_t)b*128*NP_FULL + pp;
#pragma unroll
    for (int d = 0; d < 32; d++) {
        float s = 0.f;
#pragma unroll
        for (int k = 0; k < 16; k++)
            s = fmaf(sc[k], sm[((8 + n)*32 + d)*64 + pxb + k], s);
        ob[(size_t)(n*32 + d)*NP_FULL] = s * inv;
    }
}

// ---------------- launch ----------------
extern "C" void kernel_launch(void* const* d_in, const int* in_sizes, int n_in,
                              void* d_out, int out_size) {
    const float* x          = (const float*)d_in[0];
    const float* restore_w  = (const float*)d_in[1];
    const float* restore_b  = (const float*)d_in[2];
    const float* lq_dw_w    = (const float*)d_in[3];
    const float* lq_dw_b    = (const float*)d_in[4];
    const float* lq_pw_w    = (const float*)d_in[5];
    const float* lq_pw_b    = (const float*)d_in[6];
    const float* lkv_dw_w   = (const float*)d_in[7];
    const float* lkv_dw_b   = (const float*)d_in[8];
    const float* lkv_pw_w   = (const float*)d_in[9];
    const float* lkv_pw_b   = (const float*)d_in[10];
    const float* lproj_dw_w = (const float*)d_in[11];
    const float* lproj_dw_b = (const float*)d_in[12];
    const float* lproj_pw_w = (const float*)d_in[13];
    const float* lproj_pw_b = (const float*)d_in[14];
    const float* hqkv_dw_w  = (const float*)d_in[15];
    const float* hqkv_dw_b  = (const float*)d_in[16];
    const float* hqkv_pw_w  = (const float*)d_in[17];
    const float* hqkv_pw_b  = (const float*)d_in[18];
    const float* hproj_dw_w = (const float*)d_in[19];
    const float* hproj_dw_b = (const float*)d_in[20];
    const float* hproj_pw_w = (const float*)d_in[21];
    const float* hproj_pw_b = (const float*)d_in[22];
    float* out = (float*)d_out;

    float *low, *high, *dwb, *lq, *lkvdw, *lkv, *lattn, *qkvb, *ho;
    cudaGetSymbolAddress((void**)&low,   g_low);
    cudaGetSymbolAddress((void**)&high,  g_high);
    cudaGetSymbolAddress((void**)&dwb,   g_dw);
    cudaGetSymbolAddress((void**)&lq,    g_lq);
    cudaGetSymbolAddress((void**)&lkvdw, g_lkvdw);
    cudaGetSymbolAddress((void**)&lkv,   g_lkv);
    cudaGetSymbolAddress((void**)&lattn, g_lattn);
    cudaGetSymbolAddress((void**)&qkvb,  g_qkv);
    cudaGetSymbolAddress((void**)&ho,    g_ho);

    static bool attr_done = false;
    if (!attr_done) {
        cudaFuncSetAttribute(lattn_k, cudaFuncAttributeMaxDynamicSharedMemorySize, 2*GP*32*sizeof(float));
        cudaFuncSetAttribute(hattn_k, cudaFuncAttributeMaxDynamicSharedMemorySize, 384*64*sizeof(float));
        attr_done = true;
    }

    // 1. pool
    {
        int total = BB*CC*GP;
        pool_k<<<(total + 255)/256, 256>>>(x, low);
    }
    // 2. high = restore(PS(low)) - x
    high_k<<<dim3(NP_FULL/256, BB), 256>>>(x, low, restore_w, restore_b, high);
    // 3. lq depthwise on x
    {
        int total4 = BB*CC*NP_FULL/4;
        dw_k<<<(total4 + 255)/256, 256>>>(x, lq_dw_w, lq_dw_b, dwb, CC, HH_, WW_, total4);
    }
    // 4. lq pointwise 256->128
    pw_k<<<dim3(NP_FULL/128, 1, BB), 256>>>(dwb, lq_pw_w, lq_pw_b, lq, 256, NP_FULL, 128, 0);
    // 5. lkv depthwise on low (24x24)
    {
        int total4 = BB*CC*GP/4;
        dw_k<<<(total4 + 255)/256, 256>>>(low, lkv_dw_w, lkv_dw_b, lkvdw, CC, HGD, HGD, total4);
    }
    // 6. lkv pointwise 256->256
    pw_k<<<dim3((GP + 127)/128, 2, BB), 256>>>(lkvdw, lkv_pw_w, lkv_pw_b, lkv, 256, GP, 256, 0);
    // 7. low attention
    lattn_k<<<dim3(NP_FULL/256, 4, BB), 256, 2*GP*32*sizeof(float)>>>(lq, lkv, lattn);
    // 8. lproj depthwise
    {
        int total4 = BB*128*NP_FULL/4;
        dw_k<<<(total4 + 255)/256, 256>>>(lattn, lproj_dw_w, lproj_dw_b, dwb, 128, HH_, WW_, total4);
    }
    // 9. lproj pointwise 128->128 -> out channels [0,128)
    pw_k<<<dim3(NP_FULL/128, 1, BB), 256>>>(dwb, lproj_pw_w, lproj_pw_b, out, 128, NP_FULL, 256, 0);
    // 10. hqkv depthwise on high
    {
        int total4 = BB*CC*NP_FULL/4;
        dw_k<<<(total4 + 255)/256, 256>>>(high, hqkv_dw_w, hqkv_dw_b, dwb, CC, HH_, WW_, total4);
    }
    // 11. hqkv pointwise 256->384
    pw_k<<<dim3(NP_FULL/128, 3, BB), 256>>>(dwb, hqkv_pw_w, hqkv_pw_b, qkvb, 256, NP_FULL, 384, 0);
    // 12. high windowed attention
    hattn_k<<<dim3(GP/4, BB), 256, 384*64*sizeof(float)>>>(qkvb, ho);
    // 13. hproj depthwise
    {
        int total4 = BB*128*NP_FULL/4;
        dw_k<<<(total4 + 255)/256, 256>>>(ho, hproj_dw_w, hproj_dw_b, dwb, 128, HH_, WW_, total4);
    }
    // 14. hproj pointwise 128->128 -> out channels [128,256)
    pw_k<<<dim3(NP_FULL/128, 1, BB), 256>>>(dwb, hproj_pw_w, hproj_pw_b, out, 128, NP_FULL, 256, 128);
}

// round 3
// speedup vs baseline: 1.5581x; 1.0793x over previous
#include <cuda_runtime.h>
#include <cuda_bf16.h>
#include <cstdint>

#define BB 8
#define CC 256
#define HH_ 96
#define WW_ 96
#define NP_FULL 9216   // 96*96
#define GP 576         // 24*24
#define HGD 24
#define SCALE 0.17677669529663688f   // 32^-0.5

typedef unsigned long long ull;

__device__ __forceinline__ ull pack2(float x, float y) {
    ull r;
    asm("mov.b64 %0, {%1, %2};" : "=l"(r) : "f"(x), "f"(y));
    return r;
}
__device__ __forceinline__ void unpack2(ull v, float& x, float& y) {
    asm("mov.b64 {%0, %1}, %2;" : "=f"(x), "=f"(y) : "l"(v));
}
__device__ __forceinline__ ull fma2(ull a, ull b, ull c) {
    ull d;
    asm("fma.rn.f32x2 %0, %1, %2, %3;" : "=l"(d) : "l"(a), "l"(b), "l"(c));
    return d;
}
__device__ __forceinline__ ull add2(ull a, ull b) {
    ull d;
    asm("add.rn.f32x2 %0, %1, %2;" : "=l"(d) : "l"(a), "l"(b));
    return d;
}

// ---------------- static scratch ----------------
__device__ float g_low[(size_t)BB*CC*GP];
__device__ float g_high[(size_t)BB*CC*NP_FULL];
__device__ float g_dw[(size_t)BB*CC*NP_FULL];     // low-chain dw scratch
__device__ float g_dw2[(size_t)BB*CC*NP_FULL];    // high-chain dw scratch
__device__ float g_lq[(size_t)BB*128*NP_FULL];
__device__ float g_lkvdw[(size_t)BB*CC*GP];
__device__ float g_lkv[(size_t)BB*CC*GP];
__device__ float g_lattn[(size_t)BB*128*NP_FULL];
__device__ float g_qkv[(size_t)BB*384*NP_FULL];
__device__ float g_ho[(size_t)BB*128*NP_FULL];

// ---------------- kernel 1: 4x4 avg pool ----------------
__global__ void pool_k(const float* __restrict__ x, float* __restrict__ low) {
    int i = blockIdx.x * blockDim.x + threadIdx.x;
    if (i >= BB*CC*GP) return;
    int g = i % GP; int bc = i / GP;
    int gy = g / HGD, gx = g % HGD;
    const float* xp = x + (size_t)bc*NP_FULL + (gy*4)*WW_ + gx*4;
    float s = 0.f;
#pragma unroll
    for (int r = 0; r < 4; r++) {
        float4 v = *(const float4*)(xp + r*WW_);
        s += (v.x + v.y) + (v.z + v.w);
    }
    low[i] = s * (1.0f/16.0f);
}

// ---------------- kernel 2: high = restore(pixelshuffle(low)) - x ----------------
__global__ void high_k(const float* __restrict__ x, const float* __restrict__ low,
                       const float* __restrict__ rw, const float* __restrict__ rb,
                       float* __restrict__ high) {
    __shared__ float ws[256*16];
    __shared__ float bs[256];
    int tid = threadIdx.x;
    for (int i = tid; i < 256*16; i += 256) ws[i] = rw[i];
    bs[tid] = rb[tid];
    __syncthreads();
    int b = blockIdx.y;
    int p = blockIdx.x * 256 + tid;
    int h = p / WW_, w = p % WW_;
    int off = (h & 3)*4 + (w & 3);
    int g = (h >> 2)*HGD + (w >> 2);
    ull lv2[8];
#pragma unroll
    for (int ci = 0; ci < 8; ci++) {
        float a = low[((size_t)b*CC + (2*ci+0)*16 + off)*GP + g];
        float bb2 = low[((size_t)b*CC + (2*ci+1)*16 + off)*GP + g];
        lv2[ci] = pack2(a, bb2);
    }
    const float* xp = x + (size_t)b*CC*NP_FULL + p;
    float* hp = high + (size_t)b*CC*NP_FULL + p;
    for (int oc = 0; oc < 256; oc++) {
        const ull* wrow = (const ull*)&ws[oc*16];
        ull acc = 0ull;
#pragma unroll
        for (int ci = 0; ci < 8; ci++) acc = fma2(lv2[ci], wrow[ci], acc);
        float sx, sy; unpack2(acc, sx, sy);
        float s = bs[oc] + sx + sy;
        hp[(size_t)oc*NP_FULL] = s - xp[(size_t)oc*NP_FULL];
    }
}

// ---------------- kernel 3: depthwise 3x3 pad1, 8 outputs per thread ----------------
__global__ void dw_k(const float* __restrict__ in, const float* __restrict__ w,
                     const float* __restrict__ bias, float* __restrict__ out,
                     int Ctot, int Hd, int Wd, int total8) {
    int i = blockIdx.x * blockDim.x + threadIdx.x;
    if (i >= total8) return;
    int w8 = Wd >> 3;
    int xq = i % w8; int t = i / w8;
    int y = t % Hd;
    int bcimg = t / Hd;
    int c = bcimg % Ctot;
    int x0 = xq * 8;
    const float* ip = in + (size_t)bcimg * Hd * Wd;
    const float* wp = w + c*9;
    float wv[9];
#pragma unroll
    for (int k = 0; k < 9; k++) wv[k] = __ldg(wp + k);

    float r[3][10];   // columns x0-1 .. x0+8
#pragma unroll
    for (int rr = 0; rr < 3; rr++) {
        int yy = y + rr - 1;
        bool yok = (yy >= 0) && (yy < Hd);
        const float* row = ip + yy*Wd;
        if (yok) {
            float4 m0 = *(const float4*)(row + x0);
            float4 m1 = *(const float4*)(row + x0 + 4);
            r[rr][1] = m0.x; r[rr][2] = m0.y; r[rr][3] = m0.z; r[rr][4] = m0.w;
            r[rr][5] = m1.x; r[rr][6] = m1.y; r[rr][7] = m1.z; r[rr][8] = m1.w;
            if (x0 > 0) {
                float4 L = *(const float4*)(row + x0 - 4);
                r[rr][0] = L.w;
            } else r[rr][0] = 0.f;
            if (x0 + 8 < Wd) {
                float4 R = *(const float4*)(row + x0 + 8);
                r[rr][9] = R.x;
            } else r[rr][9] = 0.f;
        } else {
#pragma unroll
            for (int j = 0; j < 10; j++) r[rr][j] = 0.f;
        }
    }
    float bvv = bias[c];
    float a[8];
#pragma unroll
    for (int j = 0; j < 8; j++) a[j] = bvv;
#pragma unroll
    for (int rr = 0; rr < 3; rr++) {
#pragma unroll
        for (int dx = 0; dx < 3; dx++) {
            float wc = wv[rr*3 + dx];
#pragma unroll
            for (int j = 0; j < 8; j++)
                a[j] = fmaf(wc, r[rr][j+dx], a[j]);
        }
    }
    float* op = out + (size_t)bcimg*Hd*Wd + y*Wd + x0;
    float4 o0; o0.x=a[0]; o0.y=a[1]; o0.z=a[2]; o0.w=a[3];
    float4 o1; o1.x=a[4]; o1.y=a[5]; o1.z=a[6]; o1.w=a[7];
    *(float4*)(op)     = o0;
    *(float4*)(op + 4) = o1;
}

// ---------------- kernel 4: pointwise 1x1 conv as tiled GEMM (f32x2) ----------------
// tile: 128 OC x 128 P, BK=16, 256 threads, 8x8 microtile via FFMA2
__global__ __launch_bounds__(256) void pw_k(
    const float* __restrict__ in, const float* __restrict__ wgt,
    const float* __restrict__ bias, float* __restrict__ out,
    int IC, int NP, int out_cstride, int out_coff) {
    __shared__ float As[16][132];
    __shared__ float Bs[16][132];
    int b = blockIdx.z;
    int oc0 = blockIdx.y * 128;
    int p0 = blockIdx.x * 128;
    int tid = threadIdx.x;
    int ty = tid >> 4, tx = tid & 15;
    const float* inb = in + (size_t)b * IC * NP;

    int a_oc = tid >> 1;
    int a_k0 = (tid & 1) * 8;
    int b_k  = tid >> 4;
    int b_p  = (tid & 15) * 8;

    ull acc[8][4];
#pragma unroll
    for (int i = 0; i < 8; i++)
#pragma unroll
        for (int j = 0; j < 4; j++) acc[i][j] = 0ull;

    for (int k0 = 0; k0 < IC; k0 += 16) {
        const float* wr = wgt + (size_t)(oc0 + a_oc)*IC + k0 + a_k0;
        float4 w0 = *(const float4*)(wr);
        float4 w1 = *(const float4*)(wr + 4);
        As[a_k0+0][a_oc] = w0.x; As[a_k0+1][a_oc] = w0.y;
        As[a_k0+2][a_oc] = w0.z; As[a_k0+3][a_oc] = w0.w;
        As[a_k0+4][a_oc] = w1.x; As[a_k0+5][a_oc] = w1.y;
        As[a_k0+6][a_oc] = w1.z; As[a_k0+7][a_oc] = w1.w;
        int pg = p0 + b_p;
        const float* brow = inb + (size_t)(k0 + b_k)*NP;
        if (pg + 7 < NP) {
            float4 b0 = *(const float4*)(brow + pg);
            float4 b1 = *(const float4*)(brow + pg + 4);
            *(float4*)&Bs[b_k][b_p]   = b0;
            *(float4*)&Bs[b_k][b_p+4] = b1;
        } else {
#pragma unroll
            for (int j = 0; j < 8; j++)
                Bs[b_k][b_p+j] = (pg + j < NP) ? brow[pg + j] : 0.f;
        }
        __syncthreads();
#pragma unroll
        for (int kk = 0; kk < 16; kk++) {
            float4 a0 = *(const float4*)&As[kk][ty*8];
            float4 a1 = *(const float4*)&As[kk][ty*8+4];
            float4 b0 = *(const float4*)&Bs[kk][tx*8];
            float4 b1 = *(const float4*)&Bs[kk][tx*8+4];
            ull bp[4];
            bp[0] = pack2(b0.x, b0.y); bp[1] = pack2(b0.z, b0.w);
            bp[2] = pack2(b1.x, b1.y); bp[3] = pack2(b1.z, b1.w);
            float aa[8] = {a0.x, a0.y, a0.z, a0.w, a1.x, a1.y, a1.z, a1.w};
#pragma unroll
            for (int i = 0; i < 8; i++) {
                ull ad = pack2(aa[i], aa[i]);
#pragma unroll
                for (int j = 0; j < 4; j++)
                    acc[i][j] = fma2(ad, bp[j], acc[i][j]);
            }
        }
        __syncthreads();
    }
    float* ob = out + (size_t)b * out_cstride * NP + (size_t)out_coff * NP;
    int pp = p0 + tx*8;
#pragma unroll
    for (int i = 0; i < 8; i++) {
        int oc = oc0 + ty*8 + i;
        float bv = __ldg(bias + oc);
        float v[8];
        unpack2(acc[i][0], v[0], v[1]);
        unpack2(acc[i][1], v[2], v[3]);
        unpack2(acc[i][2], v[4], v[5]);
        unpack2(acc[i][3], v[6], v[7]);
#pragma unroll
        for (int j = 0; j < 8; j++) v[j] += bv;
        float* orow = ob + (size_t)oc * NP;
        if (pp + 7 < NP) {
            float4 s0; s0.x=v[0]; s0.y=v[1]; s0.z=v[2]; s0.w=v[3];
            float4 s1; s1.x=v[4]; s1.y=v[5]; s1.z=v[6]; s1.w=v[7];
            *(float4*)(orow + pp) = s0;
            *(float4*)(orow + pp + 4) = s1;
        } else {
#pragma unroll
            for (int j = 0; j < 8; j++)
                if (pp + j < NP) orow[pp + j] = v[j];
        }
    }
}

// ---------------- kernel 7: low-frequency global attention (f32x2) ----------------
__global__ __launch_bounds__(256) void lattn_k(
    const float* __restrict__ q, const float* __restrict__ kv,
    float* __restrict__ o) {
    extern __shared__ float sm[];
    float* Ks = sm;
    float* Vs = sm + GP*32;
    int b = blockIdx.z, h = blockIdx.y;
    int p = blockIdx.x * 256 + threadIdx.x;
    const float* kvb = kv + ((size_t)b*256 + h*32)*GP;
    for (int i = threadIdx.x; i < GP*32; i += 256) {
        int d = i / GP, kp = i - d*GP;
        Ks[kp*32 + d] = kvb[(size_t)d*GP + kp];
        Vs[kp*32 + d] = kvb[(size_t)(128 + d)*GP + kp];
    }
    __syncthreads();
    ull q2[16];
    const float* qb = q + ((size_t)b*128 + h*32)*NP_FULL + p;
#pragma unroll
    for (int d = 0; d < 16; d++) {
        float x0 = qb[(size_t)(2*d+0)*NP_FULL];
        float x1 = qb[(size_t)(2*d+1)*NP_FULL];
        q2[d] = pack2(x0, x1);
    }
    float m = -1e30f, l = 0.f;
    ull O2[16];
#pragma unroll
    for (int d = 0; d < 16; d++) O2[d] = 0ull;

    for (int kp = 0; kp < GP; kp++) {
        const ulonglong2* k2 = (const ulonglong2*)(Ks + kp*32);
        ull a0 = 0ull, a1 = 0ull, a2 = 0ull, a3 = 0ull;
#pragma unroll
        for (int ii = 0; ii < 4; ii++) {
            ulonglong2 u0 = k2[ii*2];
            ulonglong2 u1 = k2[ii*2+1];
            a0 = fma2(q2[ii*4+0], u0.x, a0);
            a1 = fma2(q2[ii*4+1], u0.y, a1);
            a2 = fma2(q2[ii*4+2], u1.x, a2);
            a3 = fma2(q2[ii*4+3], u1.y, a3);
        }
        ull t01 = add2(a0, a1);
        ull t23 = add2(a2, a3);
        ull tt = add2(t01, t23);
        float sx, sy; unpack2(tt, sx, sy);
        float s = (sx + sy) * SCALE;
        const ulonglong2* v2 = (const ulonglong2*)(Vs + kp*32);
        if (s <= m) {
            float pe = __expf(s - m);
            l += pe;
            ull pe2 = pack2(pe, pe);
#pragma unroll
            for (int ii = 0; ii < 8; ii++) {
                ulonglong2 vv = v2[ii];
                O2[ii*2+0] = fma2(pe2, vv.x, O2[ii*2+0]);
                O2[ii*2+1] = fma2(pe2, vv.y, O2[ii*2+1]);
            }
        } else {
            float al = __expf(m - s);
            l = fmaf(l, al, 1.f);
            m = s;
            ull al2 = pack2(al, al);
#pragma unroll
            for (int ii = 0; ii < 8; ii++) {
                ulonglong2 vv = v2[ii];
                O2[ii*2+0] = fma2(O2[ii*2+0], al2, vv.x);
                O2[ii*2+1] = fma2(O2[ii*2+1], al2, vv.y);
            }
        }
    }
    float inv = 1.f / l;
    float* ob = o + ((size_t)b*128 + h*32)*NP_FULL + p;
#pragma unroll
    for (int d = 0; d < 16; d++) {
        float x0, x1; unpack2(O2[d], x0, x1);
        ob[(size_t)(2*d+0)*NP_FULL] = x0 * inv;
        ob[(size_t)(2*d+1)*NP_FULL] = x1 * inv;
    }
}

// ---------------- kernel 12: high-frequency windowed attention ----------------
__global__ __launch_bounds__(256) void hattn_k(
    const float* __restrict__ qkv, float* __restrict__ ho) {
    extern __shared__ float sm[];   // [384][64]
    int b = blockIdx.y;
    int g0 = blockIdx.x * 4;
    const float* qb = qkv + (size_t)b*384*NP_FULL;
    for (int i = threadIdx.x; i < 384*64; i += 256) {
        int c = i >> 6; int px = i & 63;
        int win = px >> 4, t = px & 15;
        int g = g0 + win; int gy = g / HGD, gx = g - gy*HGD;
        int pp = (gy*4 + (t >> 2))*WW_ + gx*4 + (t & 3);
        sm[i] = qb[(size_t)c*NP_FULL + pp];
    }
    __syncthreads();
    int tid = threadIdx.x;
    int t = tid & 15; int n = (tid >> 4) & 3; int win = tid >> 6;
    int pxb = win*16;
    float qv[32];
#pragma unroll
    for (int d = 0; d < 32; d++) qv[d] = sm[(n*32 + d)*64 + pxb + t];
    float sc[16];
    float mx = -1e30f;
#pragma unroll
    for (int k = 0; k < 16; k++) {
        float s = 0.f;
#pragma unroll
        for (int d = 0; d < 32; d++)
            s = fmaf(qv[d], sm[((4 + n)*32 + d)*64 + pxb + k], s);
        s *= SCALE;
        sc[k] = s;
        mx = fmaxf(mx, s);
    }
    float l = 0.f;
#pragma unroll
    for (int k = 0; k < 16; k++) { sc[k] = __expf(sc[k] - mx); l += sc[k]; }
    float inv = 1.f / l;
    int g = g0 + win; int gy = g / HGD, gx = g - gy*HGD;
    int pp = (gy*4 + (t >> 2))*WW_ + gx*4 + (t & 3);
    float* ob = ho + (size_t)b*128*NP_FULL + pp;
#pragma unroll
    for (int d = 0; d < 32; d++) {
        float s = 0.f;
#pragma unroll
        for (int k = 0; k < 16; k++)
            s = fmaf(sc[k], sm[((8 + n)*32 + d)*64 + pxb + k], s);
        ob[(size_t)(n*32 + d)*NP_FULL] = s * inv;
    }
}

// ---------------- launch ----------------
extern "C" void kernel_launch(void* const* d_in, const int* in_sizes, int n_in,
                              void* d_out, int out_size) {
    const float* x          = (const float*)d_in[0];
    const float* restore_w  = (const float*)d_in[1];
    const float* restore_b  = (const float*)d_in[2];
    const float* lq_dw_w    = (const float*)d_in[3];
    const float* lq_dw_b    = (const float*)d_in[4];
    const float* lq_pw_w    = (const float*)d_in[5];
    const float* lq_pw_b    = (const float*)d_in[6];
    const float* lkv_dw_w   = (const float*)d_in[7];
    const float* lkv_dw_b   = (const float*)d_in[8];
    const float* lkv_pw_w   = (const float*)d_in[9];
    const float* lkv_pw_b   = (const float*)d_in[10];
    const float* lproj_dw_w = (const float*)d_in[11];
    const float* lproj_dw_b = (const float*)d_in[12];
    const float* lproj_pw_w = (const float*)d_in[13];
    const float* lproj_pw_b = (const float*)d_in[14];
    const float* hqkv_dw_w  = (const float*)d_in[15];
    const float* hqkv_dw_b  = (const float*)d_in[16];
    const float* hqkv_pw_w  = (const float*)d_in[17];
    const float* hqkv_pw_b  = (const float*)d_in[18];
    const float* hproj_dw_w = (const float*)d_in[19];
    const float* hproj_dw_b = (const float*)d_in[20];
    const float* hproj_pw_w = (const float*)d_in[21];
    const float* hproj_pw_b = (const float*)d_in[22];
    float* out = (float*)d_out;

    float *low, *high, *dwA, *dwB, *lq, *lkvdw, *lkv, *lattn, *qkvb, *ho;
    cudaGetSymbolAddress((void**)&low,   g_low);
    cudaGetSymbolAddress((void**)&high,  g_high);
    cudaGetSymbolAddress((void**)&dwA,   g_dw);
    cudaGetSymbolAddress((void**)&dwB,   g_dw2);
    cudaGetSymbolAddress((void**)&lq,    g_lq);
    cudaGetSymbolAddress((void**)&lkvdw, g_lkvdw);
    cudaGetSymbolAddress((void**)&lkv,   g_lkv);
    cudaGetSymbolAddress((void**)&lattn, g_lattn);
    cudaGetSymbolAddress((void**)&qkvb,  g_qkv);
    cudaGetSymbolAddress((void**)&ho,    g_ho);

    static cudaStream_t s2 = nullptr;
    static cudaEvent_t evFork = nullptr, evJoin = nullptr;
    if (!s2) {
        cudaStreamCreateWithFlags(&s2, cudaStreamNonBlocking);
        cudaEventCreateWithFlags(&evFork, cudaEventDisableTiming);
        cudaEventCreateWithFlags(&evJoin, cudaEventDisableTiming);
        cudaFuncSetAttribute(lattn_k, cudaFuncAttributeMaxDynamicSharedMemorySize, 2*GP*32*sizeof(float));
        cudaFuncSetAttribute(hattn_k, cudaFuncAttributeMaxDynamicSharedMemorySize, 384*64*sizeof(float));
    }

    // ---- stream 0: pool (feeds both chains) ----
    {
        int total = BB*CC*GP;
        pool_k<<<(total + 255)/256, 256, 0>>>(x, low);
    }
    cudaEventRecord(evFork, 0);
    cudaStreamWaitEvent(s2, evFork, 0);

    // ======== HIGH chain on s2 ========
    high_k<<<dim3(NP_FULL/256, BB), 256, 0, s2>>>(x, low, restore_w, restore_b, high);
    {
        int total8 = BB*CC*NP_FULL/8;
        dw_k<<<(total8 + 255)/256, 256, 0, s2>>>(high, hqkv_dw_w, hqkv_dw_b, dwB, CC, HH_, WW_, total8);
    }
    pw_k<<<dim3(NP_FULL/128, 3, BB), 256, 0, s2>>>(dwB, hqkv_pw_w, hqkv_pw_b, qkvb, 256, NP_FULL, 384, 0);
    hattn_k<<<dim3(GP/4, BB), 256, 384*64*sizeof(float), s2>>>(qkvb, ho);
    {
        int total8 = BB*128*NP_FULL/8;
        dw_k<<<(total8 + 255)/256, 256, 0, s2>>>(ho, hproj_dw_w, hproj_dw_b, dwB, 128, HH_, WW_, total8);
    }
    pw_k<<<dim3(NP_FULL/128, 1, BB), 256, 0, s2>>>(dwB, hproj_pw_w, hproj_pw_b, out, 128, NP_FULL, 256, 128);
    cudaEventRecord(evJoin, s2);

    // ======== LOW chain on stream 0 ========
    {
        int total8 = BB*CC*NP_FULL/8;
        dw_k<<<(total8 + 255)/256, 256, 0>>>(x, lq_dw_w, lq_dw_b, dwA, CC, HH_, WW_, total8);
    }
    pw_k<<<dim3(NP_FULL/128, 1, BB), 256, 0>>>(dwA, lq_pw_w, lq_pw_b, lq, 256, NP_FULL, 128, 0);
    {
        int total8 = BB*CC*GP/8;
        dw_k<<<(total8 + 255)/256, 256, 0>>>(low, lkv_dw_w, lkv_dw_b, lkvdw, CC, HGD, HGD, total8);
    }
    pw_k<<<dim3((GP + 127)/128, 2, BB), 256, 0>>>(lkvdw, lkv_pw_w, lkv_pw_b, lkv, 256, GP, 256, 0);
    lattn_k<<<dim3(NP_FULL/256, 4, BB), 256, 2*GP*32*sizeof(float)>>>(lq, lkv, lattn);
    {
        int total8 = BB*128*NP_FULL/8;
        dw_k<<<(total8 + 255)/256, 256, 0>>>(lattn, lproj_dw_w, lproj_dw_b, dwA, 128, HH_, WW_, total8);
    }
    pw_k<<<dim3(NP_FULL/128, 1, BB), 256, 0>>>(dwA, lproj_pw_w, lproj_pw_b, out, 128, NP_FULL, 256, 0);

    // ---- join ----
    cudaStreamWaitEvent(0, evJoin, 0);
}

// round 4
// speedup vs baseline: 1.8206x; 1.1684x over previous
#include <cuda_runtime.h>
#include <cuda_bf16.h>
#include <cstdint>

#define BB 8
#define CC 256
#define HH_ 96
#define WW_ 96
#define NP_FULL 9216   // 96*96
#define GP 576         // 24*24
#define HGD 24
#define SCALE 0.17677669529663688f   // 32^-0.5

typedef unsigned long long ull;

__device__ __forceinline__ ull pack2(float x, float y) {
    ull r;
    asm("mov.b64 %0, {%1, %2};" : "=l"(r) : "f"(x), "f"(y));
    return r;
}
__device__ __forceinline__ void unpack2(ull v, float& x, float& y) {
    asm("mov.b64 {%0, %1}, %2;" : "=f"(x), "=f"(y) : "l"(v));
}
__device__ __forceinline__ ull fma2(ull a, ull b, ull c) {
    ull d;
    asm("fma.rn.f32x2 %0, %1, %2, %3;" : "=l"(d) : "l"(a), "l"(b), "l"(c));
    return d;
}
__device__ __forceinline__ ull add2(ull a, ull b) {
    ull d;
    asm("add.rn.f32x2 %0, %1, %2;" : "=l"(d) : "l"(a), "l"(b));
    return d;
}
__device__ __forceinline__ uint32_t f2tf32(float x) {
    uint32_t r;
    asm("cvt.rna.tf32.f32 %0, %1;" : "=r"(r) : "f"(x));
    return r;
}
__device__ __forceinline__ void mma_tf32(float4& d,
    uint32_t a0, uint32_t a1, uint32_t a2, uint32_t a3,
    uint32_t b0, uint32_t b1) {
    asm volatile("mma.sync.aligned.m16n8k8.row.col.f32.tf32.tf32.f32 "
        "{%0,%1,%2,%3}, {%4,%5,%6,%7}, {%8,%9}, {%0,%1,%2,%3};"
        : "+f"(d.x), "+f"(d.y), "+f"(d.z), "+f"(d.w)
        : "r"(a0), "r"(a1), "r"(a2), "r"(a3), "r"(b0), "r"(b1));
}

// ---------------- static scratch ----------------
__device__ float g_low[(size_t)BB*CC*GP];
__device__ float g_high[(size_t)BB*CC*NP_FULL];
__device__ float g_dw[(size_t)BB*CC*NP_FULL];     // low-chain dw scratch
__device__ float g_dw2[(size_t)BB*CC*NP_FULL];    // high-chain dw scratch
__device__ float g_lq[(size_t)BB*128*NP_FULL];
__device__ float g_lkvdw[(size_t)BB*CC*GP];
__device__ float g_lkv[(size_t)BB*CC*GP];
__device__ float g_lattn[(size_t)BB*128*NP_FULL];
__device__ float g_qkv[(size_t)BB*384*NP_FULL];
__device__ float g_ho[(size_t)BB*128*NP_FULL];

// ---------------- kernel 1: 4x4 avg pool ----------------
__global__ void pool_k(const float* __restrict__ x, float* __restrict__ low) {
    int i = blockIdx.x * blockDim.x + threadIdx.x;
    if (i >= BB*CC*GP) return;
    int g = i % GP; int bc = i / GP;
    int gy = g / HGD, gx = g % HGD;
    const float* xp = x + (size_t)bc*NP_FULL + (gy*4)*WW_ + gx*4;
    float s = 0.f;
#pragma unroll
    for (int r = 0; r < 4; r++) {
        float4 v = *(const float4*)(xp + r*WW_);
        s += (v.x + v.y) + (v.z + v.w);
    }
    low[i] = s * (1.0f/16.0f);
}

// ---------------- kernel 2: high = restore(pixelshuffle(low)) - x ----------------
__global__ void high_k(const float* __restrict__ x, const float* __restrict__ low,
                       const float* __restrict__ rw, const float* __restrict__ rb,
                       float* __restrict__ high) {
    __shared__ float ws[256*16];
    __shared__ float bs[256];
    int tid = threadIdx.x;
    for (int i = tid; i < 256*16; i += 256) ws[i] = rw[i];
    bs[tid] = rb[tid];
    __syncthreads();
    int b = blockIdx.y;
    int p = blockIdx.x * 256 + tid;
    int h = p / WW_, w = p % WW_;
    int off = (h & 3)*4 + (w & 3);
    int g = (h >> 2)*HGD + (w >> 2);
    ull lv2[8];
#pragma unroll
    for (int ci = 0; ci < 8; ci++) {
        float a = low[((size_t)b*CC + (2*ci+0)*16 + off)*GP + g];
        float bb2 = low[((size_t)b*CC + (2*ci+1)*16 + off)*GP + g];
        lv2[ci] = pack2(a, bb2);
    }
    const float* xp = x + (size_t)b*CC*NP_FULL + p;
    float* hp = high + (size_t)b*CC*NP_FULL + p;
    for (int oc = 0; oc < 256; oc++) {
        const ull* wrow = (const ull*)&ws[oc*16];
        ull acc = 0ull;
#pragma unroll
        for (int ci = 0; ci < 8; ci++) acc = fma2(lv2[ci], wrow[ci], acc);
        float sx, sy; unpack2(acc, sx, sy);
        float s = bs[oc] + sx + sy;
        hp[(size_t)oc*NP_FULL] = s - xp[(size_t)oc*NP_FULL];
    }
}

// ---------------- kernel 3: depthwise 3x3 pad1, 8 outputs per thread ----------------
__global__ void dw_k(const float* __restrict__ in, const float* __restrict__ w,
                     const float* __restrict__ bias, float* __restrict__ out,
                     int Ctot, int Hd, int Wd, int total8) {
    int i = blockIdx.x * blockDim.x + threadIdx.x;
    if (i >= total8) return;
    int w8 = Wd >> 3;
    int xq = i % w8; int t = i / w8;
    int y = t % Hd;
    int bcimg = t / Hd;
    int c = bcimg % Ctot;
    int x0 = xq * 8;
    const float* ip = in + (size_t)bcimg * Hd * Wd;
    const float* wp = w + c*9;
    float wv[9];
#pragma unroll
    for (int k = 0; k < 9; k++) wv[k] = __ldg(wp + k);

    float r[3][10];
#pragma unroll
    for (int rr = 0; rr < 3; rr++) {
        int yy = y + rr - 1;
        bool yok = (yy >= 0) && (yy < Hd);
        const float* row = ip + yy*Wd;
        if (yok) {
            float4 m0 = *(const float4*)(row + x0);
            float4 m1 = *(const float4*)(row + x0 + 4);
            r[rr][1] = m0.x; r[rr][2] = m0.y; r[rr][3] = m0.z; r[rr][4] = m0.w;
            r[rr][5] = m1.x; r[rr][6] = m1.y; r[rr][7] = m1.z; r[rr][8] = m1.w;
            if (x0 > 0) {
                float4 L = *(const float4*)(row + x0 - 4);
                r[rr][0] = L.w;
            } else r[rr][0] = 0.f;
            if (x0 + 8 < Wd) {
                float4 R = *(const float4*)(row + x0 + 8);
                r[rr][9] = R.x;
            } else r[rr][9] = 0.f;
        } else {
#pragma unroll
            for (int j = 0; j < 10; j++) r[rr][j] = 0.f;
        }
    }
    float bvv = bias[c];
    float a[8];
#pragma unroll
    for (int j = 0; j < 8; j++) a[j] = bvv;
#pragma unroll
    for (int rr = 0; rr < 3; rr++) {
#pragma unroll
        for (int dx = 0; dx < 3; dx++) {
            float wc = wv[rr*3 + dx];
#pragma unroll
            for (int j = 0; j < 8; j++)
                a[j] = fmaf(wc, r[rr][j+dx], a[j]);
        }
    }
    float* op = out + (size_t)bcimg*Hd*Wd + y*Wd + x0;
    float4 o0; o0.x=a[0]; o0.y=a[1]; o0.z=a[2]; o0.w=a[3];
    float4 o1; o1.x=a[4]; o1.y=a[5]; o1.z=a[6]; o1.w=a[7];
    *(float4*)(op)     = o0;
    *(float4*)(op + 4) = o1;
}

// ---------------- pointwise 1x1 conv: tf32 tensor-core GEMM ----------------
// C[OC,NP] = W[OC,IC] @ X[IC,NP]; block tile 128x128, BK=32, 8 warps (2x4),
// warp tile 64x32 = 4x4 m16n8k8 tf32 mmas per k-step.
#define PADR 136
__global__ __launch_bounds__(256) void pw_mma_k(
    const float* __restrict__ in, const float* __restrict__ wgt,
    const float* __restrict__ bias, float* __restrict__ out,
    int IC, int NP, int out_cstride, int out_coff) {
    __shared__ uint32_t As[32*PADR];   // [k][oc], tf32 bits
    __shared__ uint32_t Bs[32*PADR];   // [k][p],  tf32 bits
    int b = blockIdx.z;
    int oc0 = blockIdx.y * 128;
    int p0 = blockIdx.x * 128;
    int tid = threadIdx.x;
    int lane = tid & 31, wid = tid >> 5;
    int wm = wid >> 2, wn = wid & 3;     // 2 x 4 warp grid
    int g = lane >> 2, tig = lane & 3;
    const float* inb = in + (size_t)b * IC * NP;

    float4 acc[4][4];
#pragma unroll
    for (int i = 0; i < 4; i++)
#pragma unroll
        for (int j = 0; j < 4; j++) acc[i][j] = make_float4(0.f, 0.f, 0.f, 0.f);

    int a_oc = tid >> 1;
    int a_kb = (tid & 1) * 16;
    int b_kk = tid >> 3;
    int b_pb = (tid & 7) * 16;

    for (int k0 = 0; k0 < IC; k0 += 32) {
        // stage W[oc0..+128][k0..+32] -> As[k][oc] (transposed, tf32)
        const float* wr = wgt + (size_t)(oc0 + a_oc)*IC + k0 + a_kb;
#pragma unroll
        for (int q = 0; q < 4; q++) {
            float4 v = *(const float4*)(wr + q*4);
            int kk = a_kb + q*4;
            As[(kk+0)*PADR + a_oc] = f2tf32(v.x);
            As[(kk+1)*PADR + a_oc] = f2tf32(v.y);
            As[(kk+2)*PADR + a_oc] = f2tf32(v.z);
            As[(kk+3)*PADR + a_oc] = f2tf32(v.w);
        }
        // stage X[k0..+32][p0..+128] -> Bs[k][p] (tf32)
        const float* brow = inb + (size_t)(k0 + b_kk)*NP + p0;
#pragma unroll
        for (int q = 0; q < 4; q++) {
            int p = b_pb + q*4;
            uint4 sv;
            if (p0 + p + 3 < NP) {
                float4 v = *(const float4*)(brow + p);
                sv.x = f2tf32(v.x); sv.y = f2tf32(v.y);
                sv.z = f2tf32(v.z); sv.w = f2tf32(v.w);
            } else {
                float v0 = (p0+p+0 < NP) ? brow[p+0] : 0.f;
                float v1 = (p0+p+1 < NP) ? brow[p+1] : 0.f;
                float v2 = (p0+p+2 < NP) ? brow[p+2] : 0.f;
                float v3 = (p0+p+3 < NP) ? brow[p+3] : 0.f;
                sv.x = f2tf32(v0); sv.y = f2tf32(v1);
                sv.z = f2tf32(v2); sv.w = f2tf32(v3);
            }
            *(uint4*)&Bs[b_kk*PADR + p] = sv;
        }
        __syncthreads();
#pragma unroll
        for (int ks = 0; ks < 32; ks += 8) {
            uint32_t af[4][4];
#pragma unroll
            for (int mt = 0; mt < 4; mt++) {
                int oc = wm*64 + mt*16 + g;
                af[mt][0] = As[(ks+tig  )*PADR + oc];
                af[mt][1] = As[(ks+tig  )*PADR + oc + 8];
                af[mt][2] = As[(ks+tig+4)*PADR + oc];
                af[mt][3] = As[(ks+tig+4)*PADR + oc + 8];
            }
            uint32_t bf[4][2];
#pragma unroll
            for (int nt = 0; nt < 4; nt++) {
                int p = wn*32 + nt*8 + g;
                bf[nt][0] = Bs[(ks+tig  )*PADR + p];
                bf[nt][1] = Bs[(ks+tig+4)*PADR + p];
            }
#pragma unroll
            for (int mt = 0; mt < 4; mt++)
#pragma unroll
                for (int nt = 0; nt < 4; nt++)
                    mma_tf32(acc[mt][nt], af[mt][0], af[mt][1], af[mt][2], af[mt][3],
                             bf[nt][0], bf[nt][1]);
        }
        __syncthreads();
    }
    // epilogue
    float* ob = out + (size_t)b * out_cstride * NP + (size_t)out_coff * NP;
#pragma unroll
    for (int mt = 0; mt < 4; mt++) {
        int r0 = oc0 + wm*64 + mt*16 + g;
        int r1 = r0 + 8;
        float bv0 = __ldg(bias + r0);
        float bv1 = __ldg(bias + r1);
        float* row0 = ob + (size_t)r0 * NP;
        float* row1 = ob + (size_t)r1 * NP;
#pragma unroll
        for (int nt = 0; nt < 4; nt++) {
            int c = p0 + wn*32 + nt*8 + tig*2;
            float4 a = acc[mt][nt];
            if (c + 1 < NP) {
                float2 v0; v0.x = a.x + bv0; v0.y = a.y + bv0;
                float2 v1; v1.x = a.z + bv1; v1.y = a.w + bv1;
                *(float2*)(row0 + c) = v0;
                *(float2*)(row1 + c) = v1;
            } else if (c < NP) {
                row0[c] = a.x + bv0;
                row1[c] = a.z + bv1;
            }
        }
    }
}

// ---------------- low-frequency global attention (f32x2) ----------------
__global__ __launch_bounds__(256) void lattn_k(
    const float* __restrict__ q, const float* __restrict__ kv,
    float* __restrict__ o) {
    extern __shared__ float sm[];
    float* Ks = sm;
    float* Vs = sm + GP*32;
    int b = blockIdx.z, h = blockIdx.y;
    int p = blockIdx.x * 256 + threadIdx.x;
    const float* kvb = kv + ((size_t)b*256 + h*32)*GP;
    for (int i = threadIdx.x; i < GP*32; i += 256) {
        int d = i / GP, kp = i - d*GP;
        Ks[kp*32 + d] = kvb[(size_t)d*GP + kp];
        Vs[kp*32 + d] = kvb[(size_t)(128 + d)*GP + kp];
    }
    __syncthreads();
    ull q2[16];
    const float* qb = q + ((size_t)b*128 + h*32)*NP_FULL + p;
#pragma unroll
    for (int d = 0; d < 16; d++) {
        float x0 = qb[(size_t)(2*d+0)*NP_FULL];
        float x1 = qb[(size_t)(2*d+1)*NP_FULL];
        q2[d] = pack2(x0, x1);
    }
    float m = -1e30f, l = 0.f;
    ull O2[16];
#pragma unroll
    for (int d = 0; d < 16; d++) O2[d] = 0ull;

    for (int kp = 0; kp < GP; kp++) {
        const ulonglong2* k2 = (const ulonglong2*)(Ks + kp*32);
        ull a0 = 0ull, a1 = 0ull, a2 = 0ull, a3 = 0ull;
#pragma unroll
        for (int ii = 0; ii < 4; ii++) {
            ulonglong2 u0 = k2[ii*2];
            ulonglong2 u1 = k2[ii*2+1];
            a0 = fma2(q2[ii*4+0], u0.x, a0);
            a1 = fma2(q2[ii*4+1], u0.y, a1);
            a2 = fma2(q2[ii*4+2], u1.x, a2);
            a3 = fma2(q2[ii*4+3], u1.y, a3);
        }
        ull t01 = add2(a0, a1);
        ull t23 = add2(a2, a3);
        ull tt = add2(t01, t23);
        float sx, sy; unpack2(tt, sx, sy);
        float s = (sx + sy) * SCALE;
        const ulonglong2* v2 = (const ulonglong2*)(Vs + kp*32);
        if (s <= m) {
            float pe = __expf(s - m);
            l += pe;
            ull pe2 = pack2(pe, pe);
#pragma unroll
            for (int ii = 0; ii < 8; ii++) {
                ulonglong2 vv = v2[ii];
                O2[ii*2+0] = fma2(pe2, vv.x, O2[ii*2+0]);
                O2[ii*2+1] = fma2(pe2, vv.y, O2[ii*2+1]);
            }
        } else {
            float al = __expf(m - s);
            l = fmaf(l, al, 1.f);
            m = s;
            ull al2 = pack2(al, al);
#pragma unroll
            for (int ii = 0; ii < 8; ii++) {
                ulonglong2 vv = v2[ii];
                O2[ii*2+0] = fma2(O2[ii*2+0], al2, vv.x);
                O2[ii*2+1] = fma2(O2[ii*2+1], al2, vv.y);
            }
        }
    }
    float inv = 1.f / l;
    float* ob = o + ((size_t)b*128 + h*32)*NP_FULL + p;
#pragma unroll
    for (int d = 0; d < 16; d++) {
        float x0, x1; unpack2(O2[d], x0, x1);
        ob[(size_t)(2*d+0)*NP_FULL] = x0 * inv;
        ob[(size_t)(2*d+1)*NP_FULL] = x1 * inv;
    }
}

// ---------------- high-frequency windowed attention ----------------
__global__ __launch_bounds__(256) void hattn_k(
    const float* __restrict__ qkv, float* __restrict__ ho) {
    extern __shared__ float sm[];   // [384][64]
    int b = blockIdx.y;
    int g0 = blockIdx.x * 4;
    const float* qb = qkv + (size_t)b*384*NP_FULL;
    for (int i = threadIdx.x; i < 384*64; i += 256) {
        int c = i >> 6; int px = i & 63;
        int win = px >> 4, t = px & 15;
        int g = g0 + win; int gy = g / HGD, gx = g - gy*HGD;
        int pp = (gy*4 + (t >> 2))*WW_ + gx*4 + (t & 3);
        sm[i] = qb[(size_t)c*NP_FULL + pp];
    }
    __syncthreads();
    int tid = threadIdx.x;
    int t = tid & 15; int n = (tid >> 4) & 3; int win = tid >> 6;
    int pxb = win*16;
    float qv[32];
#pragma unroll
    for (int d = 0; d < 32; d++) qv[d] = sm[(n*32 + d)*64 + pxb + t];
    float sc[16];
    float mx = -1e30f;
#pragma unroll
    for (int k = 0; k < 16; k++) {
        float s = 0.f;
#pragma unroll
        for (int d = 0; d < 32; d++)
            s = fmaf(qv[d], sm[((4 + n)*32 + d)*64 + pxb + k], s);
        s *= SCALE;
        sc[k] = s;
        mx = fmaxf(mx, s);
    }
    float l = 0.f;
#pragma unroll
    for (int k = 0; k < 16; k++) { sc[k] = __expf(sc[k] - mx); l += sc[k]; }
    float inv = 1.f / l;
    int g = g0 + win; int gy = g / HGD, gx = g - gy*HGD;
    int pp = (gy*4 + (t >> 2))*WW_ + gx*4 + (t & 3);
    float* ob = ho + (size_t)b*128*NP_FULL + pp;
#pragma unroll
    for (int d = 0; d < 32; d++) {
        float s = 0.f;
#pragma unroll
        for (int k = 0; k < 16; k++)
            s = fmaf(sc[k], sm[((8 + n)*32 + d)*64 + pxb + k], s);
        ob[(size_t)(n*32 + d)*NP_FULL] = s * inv;
    }
}

// ---------------- launch ----------------
extern "C" void kernel_launch(void* const* d_in, const int* in_sizes, int n_in,
                              void* d_out, int out_size) {
    const float* x          = (const float*)d_in[0];
    const float* restore_w  = (const float*)d_in[1];
    const float* restore_b  = (const float*)d_in[2];
    const float* lq_dw_w    = (const float*)d_in[3];
    const float* lq_dw_b    = (const float*)d_in[4];
    const float* lq_pw_w    = (const float*)d_in[5];
    const float* lq_pw_b    = (const float*)d_in[6];
    const float* lkv_dw_w   = (const float*)d_in[7];
    const float* lkv_dw_b   = (const float*)d_in[8];
    const float* lkv_pw_w   = (const float*)d_in[9];
    const float* lkv_pw_b   = (const float*)d_in[10];
    const float* lproj_dw_w = (const float*)d_in[11];
    const float* lproj_dw_b = (const float*)d_in[12];
    const float* lproj_pw_w = (const float*)d_in[13];
    const float* lproj_pw_b = (const float*)d_in[14];
    const float* hqkv_dw_w  = (const float*)d_in[15];
    const float* hqkv_dw_b  = (const float*)d_in[16];
    const float* hqkv_pw_w  = (const float*)d_in[17];
    const float* hqkv_pw_b  = (const float*)d_in[18];
    const float* hproj_dw_w = (const float*)d_in[19];
    const float* hproj_dw_b = (const float*)d_in[20];
    const float* hproj_pw_w = (const float*)d_in[21];
    const float* hproj_pw_b = (const float*)d_in[22];
    float* out = (float*)d_out;

    float *low, *high, *dwA, *dwB, *lq, *lkvdw, *lkv, *lattn, *qkvb, *ho;
    cudaGetSymbolAddress((void**)&low,   g_low);
    cudaGetSymbolAddress((void**)&high,  g_high);
    cudaGetSymbolAddress((void**)&dwA,   g_dw);
    cudaGetSymbolAddress((void**)&dwB,   g_dw2);
    cudaGetSymbolAddress((void**)&lq,    g_lq);
    cudaGetSymbolAddress((void**)&lkvdw, g_lkvdw);
    cudaGetSymbolAddress((void**)&lkv,   g_lkv);
    cudaGetSymbolAddress((void**)&lattn, g_lattn);
    cudaGetSymbolAddress((void**)&qkvb,  g_qkv);
    cudaGetSymbolAddress((void**)&ho,    g_ho);

    static cudaStream_t s2 = nullptr;
    static cudaEvent_t evFork = nullptr, evJoin = nullptr;
    if (!s2) {
        cudaStreamCreateWithFlags(&s2, cudaStreamNonBlocking);
        cudaEventCreateWithFlags(&evFork, cudaEventDisableTiming);
        cudaEventCreateWithFlags(&evJoin, cudaEventDisableTiming);
        cudaFuncSetAttribute(lattn_k, cudaFuncAttributeMaxDynamicSharedMemorySize, 2*GP*32*sizeof(float));
        cudaFuncSetAttribute(hattn_k, cudaFuncAttributeMaxDynamicSharedMemorySize, 384*64*sizeof(float));
    }

    // ---- stream 0: pool (feeds both chains) ----
    {
        int total = BB*CC*GP;
        pool_k<<<(total + 255)/256, 256, 0>>>(x, low);
    }
    cudaEventRecord(evFork, 0);
    cudaStreamWaitEvent(s2, evFork, 0);

    // ======== HIGH chain on s2 ========
    high_k<<<dim3(NP_FULL/256, BB), 256, 0, s2>>>(x, low, restore_w, restore_b, high);
    {
        int total8 = BB*CC*NP_FULL/8;
        dw_k<<<(total8 + 255)/256, 256, 0, s2>>>(high, hqkv_dw_w, hqkv_dw_b, dwB, CC, HH_, WW_, total8);
    }
    pw_mma_k<<<dim3(NP_FULL/128, 3, BB), 256, 0, s2>>>(dwB, hqkv_pw_w, hqkv_pw_b, qkvb, 256, NP_FULL, 384, 0);
    hattn_k<<<dim3(GP/4, BB), 256, 384*64*sizeof(float), s2>>>(qkvb, ho);
    {
        int total8 = BB*128*NP_FULL/8;
        dw_k<<<(total8 + 255)/256, 256, 0, s2>>>(ho, hproj_dw_w, hproj_dw_b, dwB, 128, HH_, WW_, total8);
    }
    pw_mma_k<<<dim3(NP_FULL/128, 1, BB), 256, 0, s2>>>(dwB, hproj_pw_w, hproj_pw_b, out, 128, NP_FULL, 256, 128);
    cudaEventRecord(evJoin, s2);

    // ======== LOW chain on stream 0 ========
    {
        int total8 = BB*CC*NP_FULL/8;
        dw_k<<<(total8 + 255)/256, 256, 0>>>(x, lq_dw_w, lq_dw_b, dwA, CC, HH_, WW_, total8);
    }
    pw_mma_k<<<dim3(NP_FULL/128, 1, BB), 256, 0>>>(dwA, lq_pw_w, lq_pw_b, lq, 256, NP_FULL, 128, 0);
    {
        int total8 = BB*CC*GP/8;
        dw_k<<<(total8 + 255)/256, 256, 0>>>(low, lkv_dw_w, lkv_dw_b, lkvdw, CC, HGD, HGD, total8);
    }
    pw_mma_k<<<dim3((GP + 127)/128, 2, BB), 256, 0>>>(lkvdw, lkv_pw_w, lkv_pw_b, lkv, 256, GP, 256, 0);
    lattn_k<<<dim3(NP_FULL/256, 4, BB), 256, 2*GP*32*sizeof(float)>>>(lq, lkv, lattn);
    {
        int total8 = BB*128*NP_FULL/8;
        dw_k<<<(total8 + 255)/256, 256, 0>>>(lattn, lproj_dw_w, lproj_dw_b, dwA, 128, HH_, WW_, total8);
    }
    pw_mma_k<<<dim3(NP_FULL/128, 1, BB), 256, 0>>>(dwA, lproj_pw_w, lproj_pw_b, out, 128, NP_FULL, 256, 0);

    // ---- join ----
    cudaStreamWaitEvent(0, evJoin, 0);
}

// round 5
// speedup vs baseline: 2.7566x; 1.5141x over previous
#include <cuda_runtime.h>
#include <cuda_bf16.h>
#include <cstdint>

#define BB 8
#define CC 256
#define HH_ 96
#define WW_ 96
#define NP_FULL 9216   // 96*96
#define GP 576         // 24*24
#define HGD 24
#define SCALE 0.17677669529663688f   // 32^-0.5

typedef unsigned long long ull;

__device__ __forceinline__ ull pack2(float x, float y) {
    ull r;
    asm("mov.b64 %0, {%1, %2};" : "=l"(r) : "f"(x), "f"(y));
    return r;
}
__device__ __forceinline__ void unpack2(ull v, float& x, float& y) {
    asm("mov.b64 {%0, %1}, %2;" : "=f"(x), "=f"(y) : "l"(v));
}
__device__ __forceinline__ ull fma2(ull a, ull b, ull c) {
    ull d;
    asm("fma.rn.f32x2 %0, %1, %2, %3;" : "=l"(d) : "l"(a), "l"(b), "l"(c));
    return d;
}
__device__ __forceinline__ uint32_t f2tf32(float x) {
    uint32_t r;
    asm("cvt.rna.tf32.f32 %0, %1;" : "=r"(r) : "f"(x));
    return r;
}
__device__ __forceinline__ void mma_tf32(float4& d,
    uint32_t a0, uint32_t a1, uint32_t a2, uint32_t a3,
    uint32_t b0, uint32_t b1) {
    asm volatile("mma.sync.aligned.m16n8k8.row.col.f32.tf32.tf32.f32 "
        "{%0,%1,%2,%3}, {%4,%5,%6,%7}, {%8,%9}, {%0,%1,%2,%3};"
        : "+f"(d.x), "+f"(d.y), "+f"(d.z), "+f"(d.w)
        : "r"(a0), "r"(a1), "r"(a2), "r"(a3), "r"(b0), "r"(b1));
}

// ---------------- static scratch ----------------
__device__ float g_low[(size_t)BB*CC*GP];
__device__ float g_high[(size_t)BB*CC*NP_FULL];
__device__ float g_dw[(size_t)BB*CC*NP_FULL];
__device__ float g_dw2[(size_t)BB*CC*NP_FULL];
__device__ float g_lq[(size_t)BB*128*NP_FULL];
__device__ float g_lkvdw[(size_t)BB*CC*GP];
__device__ float g_lkv[(size_t)BB*CC*GP];
__device__ float g_lattn[(size_t)BB*128*NP_FULL];
__device__ float g_qkv[(size_t)BB*384*NP_FULL];
__device__ float g_ho[(size_t)BB*128*NP_FULL];

// ---------------- kernel 1: 4x4 avg pool ----------------
__global__ void pool_k(const float* __restrict__ x, float* __restrict__ low) {
    int i = blockIdx.x * blockDim.x + threadIdx.x;
    if (i >= BB*CC*GP) return;
    int g = i % GP; int bc = i / GP;
    int gy = g / HGD, gx = g % HGD;
    const float* xp = x + (size_t)bc*NP_FULL + (gy*4)*WW_ + gx*4;
    float s = 0.f;
#pragma unroll
    for (int r = 0; r < 4; r++) {
        float4 v = *(const float4*)(xp + r*WW_);
        s += (v.x + v.y) + (v.z + v.w);
    }
    low[i] = s * (1.0f/16.0f);
}

// ---------------- kernel 2: high = restore(pixelshuffle(low)) - x ----------------
__global__ void high_k(const float* __restrict__ x, const float* __restrict__ low,
                       const float* __restrict__ rw, const float* __restrict__ rb,
                       float* __restrict__ high) {
    __shared__ float ws[256*16];
    __shared__ float bs[256];
    int tid = threadIdx.x;
    for (int i = tid; i < 256*16; i += 256) ws[i] = rw[i];
    bs[tid] = rb[tid];
    __syncthreads();
    int b = blockIdx.y;
    int p = blockIdx.x * 256 + tid;
    int h = p / WW_, w = p % WW_;
    int off = (h & 3)*4 + (w & 3);
    int g = (h >> 2)*HGD + (w >> 2);
    ull lv2[8];
#pragma unroll
    for (int ci = 0; ci < 8; ci++) {
        float a = low[((size_t)b*CC + (2*ci+0)*16 + off)*GP + g];
        float bb2 = low[((size_t)b*CC + (2*ci+1)*16 + off)*GP + g];
        lv2[ci] = pack2(a, bb2);
    }
    const float* xp = x + (size_t)b*CC*NP_FULL + p;
    float* hp = high + (size_t)b*CC*NP_FULL + p;
    for (int oc = 0; oc < 256; oc++) {
        const ull* wrow = (const ull*)&ws[oc*16];
        ull acc = 0ull;
#pragma unroll
        for (int ci = 0; ci < 8; ci++) acc = fma2(lv2[ci], wrow[ci], acc);
        float sx, sy; unpack2(acc, sx, sy);
        float s = bs[oc] + sx + sy;
        hp[(size_t)oc*NP_FULL] = s - xp[(size_t)oc*NP_FULL];
    }
}

// ---------------- kernel 3: depthwise 3x3 pad1, 8 outputs per thread ----------------
__global__ void dw_k(const float* __restrict__ in, const float* __restrict__ w,
                     const float* __restrict__ bias, float* __restrict__ out,
                     int Ctot, int Hd, int Wd, int total8) {
    int i = blockIdx.x * blockDim.x + threadIdx.x;
    if (i >= total8) return;
    int w8 = Wd >> 3;
    int xq = i % w8; int t = i / w8;
    int y = t % Hd;
    int bcimg = t / Hd;
    int c = bcimg % Ctot;
    int x0 = xq * 8;
    const float* ip = in + (size_t)bcimg * Hd * Wd;
    const float* wp = w + c*9;
    float wv[9];
#pragma unroll
    for (int k = 0; k < 9; k++) wv[k] = __ldg(wp + k);

    float r[3][10];
#pragma unroll
    for (int rr = 0; rr < 3; rr++) {
        int yy = y + rr - 1;
        bool yok = (yy >= 0) && (yy < Hd);
        const float* row = ip + yy*Wd;
        if (yok) {
            float4 m0 = *(const float4*)(row + x0);
            float4 m1 = *(const float4*)(row + x0 + 4);
            r[rr][1] = m0.x; r[rr][2] = m0.y; r[rr][3] = m0.z; r[rr][4] = m0.w;
            r[rr][5] = m1.x; r[rr][6] = m1.y; r[rr][7] = m1.z; r[rr][8] = m1.w;
            if (x0 > 0) {
                float4 L = *(const float4*)(row + x0 - 4);
                r[rr][0] = L.w;
            } else r[rr][0] = 0.f;
            if (x0 + 8 < Wd) {
                float4 R = *(const float4*)(row + x0 + 8);
                r[rr][9] = R.x;
            } else r[rr][9] = 0.f;
        } else {
#pragma unroll
            for (int j = 0; j < 10; j++) r[rr][j] = 0.f;
        }
    }
    float bvv = bias[c];
    float a[8];
#pragma unroll
    for (int j = 0; j < 8; j++) a[j] = bvv;
#pragma unroll
    for (int rr = 0; rr < 3; rr++) {
#pragma unroll
        for (int dx = 0; dx < 3; dx++) {
            float wc = wv[rr*3 + dx];
#pragma unroll
            for (int j = 0; j < 8; j++)
                a[j] = fmaf(wc, r[rr][j+dx], a[j]);
        }
    }
    float* op = out + (size_t)bcimg*Hd*Wd + y*Wd + x0;
    float4 o0; o0.x=a[0]; o0.y=a[1]; o0.z=a[2]; o0.w=a[3];
    float4 o1; o1.x=a[4]; o1.y=a[5]; o1.z=a[6]; o1.w=a[7];
    *(float4*)(op)     = o0;
    *(float4*)(op + 4) = o1;
}

// ---------------- pointwise 1x1 conv: tf32 tensor-core GEMM ----------------
#define PADR 136
__global__ __launch_bounds__(256) void pw_mma_k(
    const float* __restrict__ in, const float* __restrict__ wgt,
    const float* __restrict__ bias, float* __restrict__ out,
    int IC, int NP, int out_cstride, int out_coff) {
    __shared__ uint32_t As[32*PADR];
    __shared__ uint32_t Bs[32*PADR];
    int b = blockIdx.z;
    int oc0 = blockIdx.y * 128;
    int p0 = blockIdx.x * 128;
    int tid = threadIdx.x;
    int lane = tid & 31, wid = tid >> 5;
    int wm = wid >> 2, wn = wid & 3;
    int g = lane >> 2, tig = lane & 3;
    const float* inb = in + (size_t)b * IC * NP;

    float4 acc[4][4];
#pragma unroll
    for (int i = 0; i < 4; i++)
#pragma unroll
        for (int j = 0; j < 4; j++) acc[i][j] = make_float4(0.f, 0.f, 0.f, 0.f);

    int a_oc = tid >> 1;
    int a_kb = (tid & 1) * 16;
    int b_kk = tid >> 3;
    int b_pb = (tid & 7) * 16;

    for (int k0 = 0; k0 < IC; k0 += 32) {
        const float* wr = wgt + (size_t)(oc0 + a_oc)*IC + k0 + a_kb;
#pragma unroll
        for (int q = 0; q < 4; q++) {
            float4 v = *(const float4*)(wr + q*4);
            int kk = a_kb + q*4;
            As[(kk+0)*PADR + a_oc] = f2tf32(v.x);
            As[(kk+1)*PADR + a_oc] = f2tf32(v.y);
            As[(kk+2)*PADR + a_oc] = f2tf32(v.z);
            As[(kk+3)*PADR + a_oc] = f2tf32(v.w);
        }
        const float* brow = inb + (size_t)(k0 + b_kk)*NP + p0;
#pragma unroll
        for (int q = 0; q < 4; q++) {
            int p = b_pb + q*4;
            uint4 sv;
            if (p0 + p + 3 < NP) {
                float4 v = *(const float4*)(brow + p);
                sv.x = f2tf32(v.x); sv.y = f2tf32(v.y);
                sv.z = f2tf32(v.z); sv.w = f2tf32(v.w);
            } else {
                float v0 = (p0+p+0 < NP) ? brow[p+0] : 0.f;
                float v1 = (p0+p+1 < NP) ? brow[p+1] : 0.f;
                float v2 = (p0+p+2 < NP) ? brow[p+2] : 0.f;
                float v3 = (p0+p+3 < NP) ? brow[p+3] : 0.f;
                sv.x = f2tf32(v0); sv.y = f2tf32(v1);
                sv.z = f2tf32(v2); sv.w = f2tf32(v3);
            }
            *(uint4*)&Bs[b_kk*PADR + p] = sv;
        }
        __syncthreads();
#pragma unroll
        for (int ks = 0; ks < 32; ks += 8) {
            uint32_t af[4][4];
#pragma unroll
            for (int mt = 0; mt < 4; mt++) {
                int oc = wm*64 + mt*16 + g;
                af[mt][0] = As[(ks+tig  )*PADR + oc];
                af[mt][1] = As[(ks+tig  )*PADR + oc + 8];
                af[mt][2] = As[(ks+tig+4)*PADR + oc];
                af[mt][3] = As[(ks+tig+4)*PADR + oc + 8];
            }
            uint32_t bf[4][2];
#pragma unroll
            for (int nt = 0; nt < 4; nt++) {
                int p = wn*32 + nt*8 + g;
                bf[nt][0] = Bs[(ks+tig  )*PADR + p];
                bf[nt][1] = Bs[(ks+tig+4)*PADR + p];
            }
#pragma unroll
            for (int mt = 0; mt < 4; mt++)
#pragma unroll
                for (int nt = 0; nt < 4; nt++)
                    mma_tf32(acc[mt][nt], af[mt][0], af[mt][1], af[mt][2], af[mt][3],
                             bf[nt][0], bf[nt][1]);
        }
        __syncthreads();
    }
    float* ob = out + (size_t)b * out_cstride * NP + (size_t)out_coff * NP;
#pragma unroll
    for (int mt = 0; mt < 4; mt++) {
        int r0 = oc0 + wm*64 + mt*16 + g;
        int r1 = r0 + 8;
        float bv0 = __ldg(bias + r0);
        float bv1 = __ldg(bias + r1);
        float* row0 = ob + (size_t)r0 * NP;
        float* row1 = ob + (size_t)r1 * NP;
#pragma unroll
        for (int nt = 0; nt < 4; nt++) {
            int c = p0 + wn*32 + nt*8 + tig*2;
            float4 a = acc[mt][nt];
            if (c + 1 < NP) {
                float2 v0; v0.x = a.x + bv0; v0.y = a.y + bv0;
                float2 v1; v1.x = a.z + bv1; v1.y = a.w + bv1;
                *(float2*)(row0 + c) = v0;
                *(float2*)(row1 + c) = v1;
            } else if (c < NP) {
                row0[c] = a.x + bv0;
                row1[c] = a.z + bv1;
            }
        }
    }
}

// ---------------- low-frequency global attention: flash tf32 MMA ----------------
// block: 128 q-rows x one (b,h); 8 warps, warp = 16 q-rows.
// smem words: Ps/Qs [0,8704), Ks [8704,27392) stride 584, Vs [27392,50432) stride 40
#define LSM_WORDS 50432
__global__ __launch_bounds__(256) void lattn_mma_k(
    const float* __restrict__ q, const float* __restrict__ kv,
    float* __restrict__ o) {
    extern __shared__ uint32_t S[];
    uint32_t* Ps = S;                 // also Q staging (stride 36)
    uint32_t* Ks = S + 8704;          // [32][584]
    uint32_t* Vs = S + 27392;         // [576][40]
    int b = blockIdx.z, h = blockIdx.y;
    int p0 = blockIdx.x * 128;
    int tid = threadIdx.x;
    int lane = tid & 31, w = tid >> 5;
    int g = lane >> 2, tig = lane & 3;
    const float* qb  = q  + ((size_t)b*128 + h*32)*NP_FULL;
    const float* kvb = kv + ((size_t)b*256 + h*32)*GP;

    // stage Q (SCALE folded), K, V as tf32
    for (int i = tid; i < 128*32; i += 256) {
        int d = i >> 7, pix = i & 127;
        Ps[pix*36 + d] = f2tf32(qb[(size_t)d*NP_FULL + p0 + pix] * SCALE);
    }
    for (int i = tid; i < 576*32; i += 256) {
        int d = i / 576, kp = i - d*576;
        Ks[d*584 + kp] = f2tf32(kvb[(size_t)d*GP + kp]);
    }
    for (int i = tid; i < 576*32; i += 256) {
        int d = i / 576, kp = i - d*576;
        Vs[kp*40 + d] = f2tf32(kvb[(size_t)(128 + d)*GP + kp]);
    }
    __syncthreads();

    int r0 = w*16 + g;
    uint32_t aq[4][4];
#pragma unroll
    for (int kt = 0; kt < 4; kt++) {
        aq[kt][0] = Ps[(r0  )*36 + kt*8 + tig];
        aq[kt][1] = Ps[(r0+8)*36 + kt*8 + tig];
        aq[kt][2] = Ps[(r0  )*36 + kt*8 + tig + 4];
        aq[kt][3] = Ps[(r0+8)*36 + kt*8 + tig + 4];
    }
    __syncwarp();

    float4 oacc[4];
#pragma unroll
    for (int dt = 0; dt < 4; dt++) oacc[dt] = make_float4(0.f,0.f,0.f,0.f);
    float m0 = -1e30f, m1 = -1e30f, l0 = 0.f, l1 = 0.f;

    for (int c = 0; c < 9; c++) {
        int kb = c*64;
        float4 s[8];
#pragma unroll
        for (int nt = 0; nt < 8; nt++) s[nt] = make_float4(0.f,0.f,0.f,0.f);
#pragma unroll
        for (int kt = 0; kt < 4; kt++) {
#pragma unroll
            for (int nt = 0; nt < 8; nt++) {
                uint32_t b0 = Ks[(kt*8+tig  )*584 + kb + nt*8 + g];
                uint32_t b1 = Ks[(kt*8+tig+4)*584 + kb + nt*8 + g];
                mma_tf32(s[nt], aq[kt][0], aq[kt][1], aq[kt][2], aq[kt][3], b0, b1);
            }
        }
        // online softmax
        float mx0 = -1e30f, mx1 = -1e30f;
#pragma unroll
        for (int nt = 0; nt < 8; nt++) {
            mx0 = fmaxf(mx0, fmaxf(s[nt].x, s[nt].y));
            mx1 = fmaxf(mx1, fmaxf(s[nt].z, s[nt].w));
        }
        mx0 = fmaxf(mx0, __shfl_xor_sync(0xffffffffu, mx0, 1));
        mx0 = fmaxf(mx0, __shfl_xor_sync(0xffffffffu, mx0, 2));
        mx1 = fmaxf(mx1, __shfl_xor_sync(0xffffffffu, mx1, 1));
        mx1 = fmaxf(mx1, __shfl_xor_sync(0xffffffffu, mx1, 2));
        float nm0 = fmaxf(m0, mx0), nm1 = fmaxf(m1, mx1);
        float al0 = __expf(m0 - nm0), al1 = __expf(m1 - nm1);
        m0 = nm0; m1 = nm1;
        float sum0 = 0.f, sum1 = 0.f;
#pragma unroll
        for (int nt = 0; nt < 8; nt++) {
            s[nt].x = __expf(s[nt].x - m0); sum0 += s[nt].x;
            s[nt].y = __expf(s[nt].y - m0); sum0 += s[nt].y;
            s[nt].z = __expf(s[nt].z - m1); sum1 += s[nt].z;
            s[nt].w = __expf(s[nt].w - m1); sum1 += s[nt].w;
        }
        l0 = l0*al0 + sum0;
        l1 = l1*al1 + sum1;
#pragma unroll
        for (int dt = 0; dt < 4; dt++) {
            oacc[dt].x *= al0; oacc[dt].y *= al0;
            oacc[dt].z *= al1; oacc[dt].w *= al1;
        }
        // stage P (own rows only)
        __syncwarp();
#pragma unroll
        for (int nt = 0; nt < 8; nt++) {
            uint2 u0; u0.x = f2tf32(s[nt].x); u0.y = f2tf32(s[nt].y);
            uint2 u1; u1.x = f2tf32(s[nt].z); u1.y = f2tf32(s[nt].w);
            *(uint2*)&Ps[(r0  )*68 + nt*8 + 2*tig] = u0;
            *(uint2*)&Ps[(r0+8)*68 + nt*8 + 2*tig] = u1;
        }
        __syncwarp();
        // O += P @ V
#pragma unroll
        for (int kt2 = 0; kt2 < 8; kt2++) {
            uint32_t a0 = Ps[(r0  )*68 + kt2*8 + tig];
            uint32_t a1 = Ps[(r0+8)*68 + kt2*8 + tig];
            uint32_t a2 = Ps[(r0  )*68 + kt2*8 + tig + 4];
            uint32_t a3 = Ps[(r0+8)*68 + kt2*8 + tig + 4];
#pragma unroll
            for (int dt = 0; dt < 4; dt++) {
                uint32_t b0 = Vs[(kb + kt2*8 + tig  )*40 + dt*8 + g];
                uint32_t b1 = Vs[(kb + kt2*8 + tig+4)*40 + dt*8 + g];
                mma_tf32(oacc[dt], a0, a1, a2, a3, b0, b1);
            }
        }
    }
    l0 += __shfl_xor_sync(0xffffffffu, l0, 1);
    l0 += __shfl_xor_sync(0xffffffffu, l0, 2);
    l1 += __shfl_xor_sync(0xffffffffu, l1, 1);
    l1 += __shfl_xor_sync(0xffffffffu, l1, 2);
    float inv0 = 1.f / l0, inv1 = 1.f / l1;
    float* ob = o + ((size_t)b*128 + h*32)*NP_FULL + p0;
#pragma unroll
    for (int dt = 0; dt < 4; dt++) {
        int d0 = dt*8 + 2*tig;
        ob[(size_t)(d0  )*NP_FULL + r0    ] = oacc[dt].x * inv0;
        ob[(size_t)(d0+1)*NP_FULL + r0    ] = oacc[dt].y * inv0;
        ob[(size_t)(d0  )*NP_FULL + r0 + 8] = oacc[dt].z * inv1;
        ob[(size_t)(d0+1)*NP_FULL + r0 + 8] = oacc[dt].w * inv1;
    }
}

// ---------------- high-frequency windowed attention ----------------
__global__ __launch_bounds__(256) void hattn_k(
    const float* __restrict__ qkv, float* __restrict__ ho) {
    extern __shared__ float sm[];   // [384][64]
    int b = blockIdx.y;
    int g0 = blockIdx.x * 4;
    const float* qb = qkv + (size_t)b*384*NP_FULL;
    for (int i = threadIdx.x; i < 384*64; i += 256) {
        int c = i >> 6; int px = i & 63;
        int win = px >> 4, t = px & 15;
        int g = g0 + win; int gy = g / HGD, gx = g - gy*HGD;
        int pp = (gy*4 + (t >> 2))*WW_ + gx*4 + (t & 3);
        sm[i] = qb[(size_t)c*NP_FULL + pp];
    }
    __syncthreads();
    int tid = threadIdx.x;
    int t = tid & 15; int n = (tid >> 4) & 3; int win = tid >> 6;
    int pxb = win*16;
    float qv[32];
#pragma unroll
    for (int d = 0; d < 32; d++) qv[d] = sm[(n*32 + d)*64 + pxb + t];
    float sc[16];
    float mx = -1e30f;
#pragma unroll
    for (int k = 0; k < 16; k++) {
        float s = 0.f;
#pragma unroll
        for (int d = 0; d < 32; d++)
            s = fmaf(qv[d], sm[((4 + n)*32 + d)*64 + pxb + k], s);
        s *= SCALE;
        sc[k] = s;
        mx = fmaxf(mx, s);
    }
    float l = 0.f;
#pragma unroll
    for (int k = 0; k < 16; k++) { sc[k] = __expf(sc[k] - mx); l += sc[k]; }
    float inv = 1.f / l;
    int g = g0 + win; int gy = g / HGD, gx = g - gy*HGD;
    int pp = (gy*4 + (t >> 2))*WW_ + gx*4 + (t & 3);
    float* ob = ho + (size_t)b*128*NP_FULL + pp;
#pragma unroll
    for (int d = 0; d < 32; d++) {
        float s = 0.f;
#pragma unroll
        for (int k = 0; k < 16; k++)
            s = fmaf(sc[k], sm[((8 + n)*32 + d)*64 + pxb + k], s);
        ob[(size_t)(n*32 + d)*NP_FULL] = s * inv;
    }
}

// ---------------- launch ----------------
extern "C" void kernel_launch(void* const* d_in, const int* in_sizes, int n_in,
                              void* d_out, int out_size) {
    const float* x          = (const float*)d_in[0];
    const float* restore_w  = (const float*)d_in[1];
    const float* restore_b  = (const float*)d_in[2];
    const float* lq_dw_w    = (const float*)d_in[3];
    const float* lq_dw_b    = (const float*)d_in[4];
    const float* lq_pw_w    = (const float*)d_in[5];
    const float* lq_pw_b    = (const float*)d_in[6];
    const float* lkv_dw_w   = (const float*)d_in[7];
    const float* lkv_dw_b   = (const float*)d_in[8];
    const float* lkv_pw_w   = (const float*)d_in[9];
    const float* lkv_pw_b   = (const float*)d_in[10];
    const float* lproj_dw_w = (const float*)d_in[11];
    const float* lproj_dw_b = (const float*)d_in[12];
    const float* lproj_pw_w = (const float*)d_in[13];
    const float* lproj_pw_b = (const float*)d_in[14];
    const float* hqkv_dw_w  = (const float*)d_in[15];
    const float* hqkv_dw_b  = (const float*)d_in[16];
    const float* hqkv_pw_w  = (const float*)d_in[17];
    const float* hqkv_pw_b  = (const float*)d_in[18];
    const float* hproj_dw_w = (const float*)d_in[19];
    const float* hproj_dw_b = (const float*)d_in[20];
    const float* hproj_pw_w = (const float*)d_in[21];
    const float* hproj_pw_b = (const float*)d_in[22];
    float* out = (float*)d_out;

    float *low, *high, *dwA, *dwB, *lq, *lkvdw, *lkv, *lattn, *qkvb, *ho;
    cudaGetSymbolAddress((void**)&low,   g_low);
    cudaGetSymbolAddress((void**)&high,  g_high);
    cudaGetSymbolAddress((void**)&dwA,   g_dw);
    cudaGetSymbolAddress((void**)&dwB,   g_dw2);
    cudaGetSymbolAddress((void**)&lq,    g_lq);
    cudaGetSymbolAddress((void**)&lkvdw, g_lkvdw);
    cudaGetSymbolAddress((void**)&lkv,   g_lkv);
    cudaGetSymbolAddress((void**)&lattn, g_lattn);
    cudaGetSymbolAddress((void**)&qkvb,  g_qkv);
    cudaGetSymbolAddress((void**)&ho,    g_ho);

    static cudaStream_t s2 = nullptr;
    static cudaEvent_t evFork = nullptr, evJoin = nullptr;
    if (!s2) {
        cudaStreamCreateWithFlags(&s2, cudaStreamNonBlocking);
        cudaEventCreateWithFlags(&evFork, cudaEventDisableTiming);
        cudaEventCreateWithFlags(&evJoin, cudaEventDisableTiming);
        cudaFuncSetAttribute(lattn_mma_k, cudaFuncAttributeMaxDynamicSharedMemorySize, LSM_WORDS*4);
        cudaFuncSetAttribute(hattn_k, cudaFuncAttributeMaxDynamicSharedMemorySize, 384*64*sizeof(float));
    }

    // ---- stream 0: pool (feeds both chains) ----
    {
        int total = BB*CC*GP;
        pool_k<<<(total + 255)/256, 256, 0>>>(x, low);
    }
    cudaEventRecord(evFork, 0);
    cudaStreamWaitEvent(s2, evFork, 0);

    // ======== HIGH chain on s2 ========
    high_k<<<dim3(NP_FULL/256, BB), 256, 0, s2>>>(x, low, restore_w, restore_b, high);
    {
        int total8 = BB*CC*NP_FULL/8;
        dw_k<<<(total8 + 255)/256, 256, 0, s2>>>(high, hqkv_dw_w, hqkv_dw_b, dwB, CC, HH_, WW_, total8);
    }
    pw_mma_k<<<dim3(NP_FULL/128, 3, BB), 256, 0, s2>>>(dwB, hqkv_pw_w, hqkv_pw_b, qkvb, 256, NP_FULL, 384, 0);
    hattn_k<<<dim3(GP/4, BB), 256, 384*64*sizeof(float), s2>>>(qkvb, ho);
    {
        int total8 = BB*128*NP_FULL/8;
        dw_k<<<(total8 + 255)/256, 256, 0, s2>>>(ho, hproj_dw_w, hproj_dw_b, dwB, 128, HH_, WW_, total8);
    }
    pw_mma_k<<<dim3(NP_FULL/128, 1, BB), 256, 0, s2>>>(dwB, hproj_pw_w, hproj_pw_b, out, 128, NP_FULL, 256, 128);
    cudaEventRecord(evJoin, s2);

    // ======== LOW chain on stream 0 ========
    {
        int total8 = BB*CC*NP_FULL/8;
        dw_k<<<(total8 + 255)/256, 256, 0>>>(x, lq_dw_w, lq_dw_b, dwA, CC, HH_, WW_, total8);
    }
    pw_mma_k<<<dim3(NP_FULL/128, 1, BB), 256, 0>>>(dwA, lq_pw_w, lq_pw_b, lq, 256, NP_FULL, 128, 0);
    {
        int total8 = BB*CC*GP/8;
        dw_k<<<(total8 + 255)/256, 256, 0>>>(low, lkv_dw_w, lkv_dw_b, lkvdw, CC, HGD, HGD, total8);
    }
    pw_mma_k<<<dim3((GP + 127)/128, 2, BB), 256, 0>>>(lkvdw, lkv_pw_w, lkv_pw_b, lkv, 256, GP, 256, 0);
    lattn_mma_k<<<dim3(NP_FULL/128, 4, BB), 256, LSM_WORDS*4>>>(lq, lkv, lattn);
    {
        int total8 = BB*128*NP_FULL/8;
        dw_k<<<(total8 + 255)/256, 256, 0>>>(lattn, lproj_dw_w, lproj_dw_b, dwA, 128, HH_, WW_, total8);
    }
    pw_mma_k<<<dim3(NP_FULL/128, 1, BB), 256, 0>>>(dwA, lproj_pw_w, lproj_pw_b, out, 128, NP_FULL, 256, 0);

    // ---- join ----
    cudaStreamWaitEvent(0, evJoin, 0);
}

// round 6
// speedup vs baseline: 2.8217x; 1.0236x over previous
#include <cuda_runtime.h>
#include <cuda_bf16.h>
#include <cstdint>

#define BB 8
#define CC 256
#define HH_ 96
#define WW_ 96
#define NP_FULL 9216   // 96*96
#define GP 576         // 24*24
#define HGD 24
#define SCALE 0.17677669529663688f   // 32^-0.5

typedef unsigned long long ull;

__device__ __forceinline__ ull pack2(float x, float y) {
    ull r;
    asm("mov.b64 %0, {%1, %2};" : "=l"(r) : "f"(x), "f"(y));
    return r;
}
__device__ __forceinline__ void unpack2(ull v, float& x, float& y) {
    asm("mov.b64 {%0, %1}, %2;" : "=f"(x), "=f"(y) : "l"(v));
}
__device__ __forceinline__ ull fma2(ull a, ull b, ull c) {
    ull d;
    asm("fma.rn.f32x2 %0, %1, %2, %3;" : "=l"(d) : "l"(a), "l"(b), "l"(c));
    return d;
}
__device__ __forceinline__ uint32_t f2tf32(float x) {
    uint32_t r;
    asm("cvt.rna.tf32.f32 %0, %1;" : "=r"(r) : "f"(x));
    return r;
}
__device__ __forceinline__ void mma_tf32(float4& d,
    uint32_t a0, uint32_t a1, uint32_t a2, uint32_t a3,
    uint32_t b0, uint32_t b1) {
    asm volatile("mma.sync.aligned.m16n8k8.row.col.f32.tf32.tf32.f32 "
        "{%0,%1,%2,%3}, {%4,%5,%6,%7}, {%8,%9}, {%0,%1,%2,%3};"
        : "+f"(d.x), "+f"(d.y), "+f"(d.z), "+f"(d.w)
        : "r"(a0), "r"(a1), "r"(a2), "r"(a3), "r"(b0), "r"(b1));
}
__device__ __forceinline__ void cp16(uint32_t dst_smem, const float* src) {
    asm volatile("cp.async.cg.shared.global [%0], [%1], 16;"
                 :: "r"(dst_smem), "l"(src));
}
__device__ __forceinline__ void cp16z(uint32_t dst_smem, const float* src, int nbytes) {
    asm volatile("cp.async.cg.shared.global [%0], [%1], 16, %2;"
                 :: "r"(dst_smem), "l"(src), "r"(nbytes));
}

// ---------------- static scratch ----------------
__device__ float g_low[(size_t)BB*CC*GP];
__device__ float g_high[(size_t)BB*CC*NP_FULL];
__device__ float g_dw[(size_t)BB*CC*NP_FULL];
__device__ float g_dw2[(size_t)BB*CC*NP_FULL];
__device__ float g_lq[(size_t)BB*128*NP_FULL];
__device__ float g_lkvdw[(size_t)BB*CC*GP];
__device__ float g_lkv[(size_t)BB*CC*GP];
__device__ float g_lattn[(size_t)BB*128*NP_FULL];
__device__ float g_qkv[(size_t)BB*384*NP_FULL];
__device__ float g_ho[(size_t)BB*128*NP_FULL];

// ---------------- kernel 1: 4x4 avg pool ----------------
__global__ void pool_k(const float* __restrict__ x, float* __restrict__ low) {
    int i = blockIdx.x * blockDim.x + threadIdx.x;
    if (i >= BB*CC*GP) return;
    int g = i % GP; int bc = i / GP;
    int gy = g / HGD, gx = g % HGD;
    const float* xp = x + (size_t)bc*NP_FULL + (gy*4)*WW_ + gx*4;
    float s = 0.f;
#pragma unroll
    for (int r = 0; r < 4; r++) {
        float4 v = *(const float4*)(xp + r*WW_);
        s += (v.x + v.y) + (v.z + v.w);
    }
    low[i] = s * (1.0f/16.0f);
}

// ---------------- kernel 2: high = restore(pixelshuffle(low)) - x ----------------
__global__ void high_k(const float* __restrict__ x, const float* __restrict__ low,
                       const float* __restrict__ rw, const float* __restrict__ rb,
                       float* __restrict__ high) {
    __shared__ float ws[256*16];
    __shared__ float bs[256];
    int tid = threadIdx.x;
    for (int i = tid; i < 256*16; i += 256) ws[i] = rw[i];
    bs[tid] = rb[tid];
    __syncthreads();
    int b = blockIdx.y;
    int p = blockIdx.x * 256 + tid;
    int h = p / WW_, w = p % WW_;
    int off = (h & 3)*4 + (w & 3);
    int g = (h >> 2)*HGD + (w >> 2);
    ull lv2[8];
#pragma unroll
    for (int ci = 0; ci < 8; ci++) {
        float a = low[((size_t)b*CC + (2*ci+0)*16 + off)*GP + g];
        float bb2 = low[((size_t)b*CC + (2*ci+1)*16 + off)*GP + g];
        lv2[ci] = pack2(a, bb2);
    }
    const float* xp = x + (size_t)b*CC*NP_FULL + p;
    float* hp = high + (size_t)b*CC*NP_FULL + p;
    for (int oc = 0; oc < 256; oc++) {
        const ull* wrow = (const ull*)&ws[oc*16];
        ull acc = 0ull;
#pragma unroll
        for (int ci = 0; ci < 8; ci++) acc = fma2(lv2[ci], wrow[ci], acc);
        float sx, sy; unpack2(acc, sx, sy);
        float s = bs[oc] + sx + sy;
        hp[(size_t)oc*NP_FULL] = s - xp[(size_t)oc*NP_FULL];
    }
}

// ---------------- kernel 3: depthwise 3x3 pad1, 8 outputs per thread ----------------
__global__ void dw_k(const float* __restrict__ in, const float* __restrict__ w,
                     const float* __restrict__ bias, float* __restrict__ out,
                     int Ctot, int Hd, int Wd, int total8) {
    int i = blockIdx.x * blockDim.x + threadIdx.x;
    if (i >= total8) return;
    int w8 = Wd >> 3;
    int xq = i % w8; int t = i / w8;
    int y = t % Hd;
    int bcimg = t / Hd;
    int c = bcimg % Ctot;
    int x0 = xq * 8;
    const float* ip = in + (size_t)bcimg * Hd * Wd;
    const float* wp = w + c*9;
    float wv[9];
#pragma unroll
    for (int k = 0; k < 9; k++) wv[k] = __ldg(wp + k);

    float r[3][10];
#pragma unroll
    for (int rr = 0; rr < 3; rr++) {
        int yy = y + rr - 1;
        bool yok = (yy >= 0) && (yy < Hd);
        const float* row = ip + yy*Wd;
        if (yok) {
            float4 m0 = *(const float4*)(row + x0);
            float4 m1 = *(const float4*)(row + x0 + 4);
            r[rr][1] = m0.x; r[rr][2] = m0.y; r[rr][3] = m0.z; r[rr][4] = m0.w;
            r[rr][5] = m1.x; r[rr][6] = m1.y; r[rr][7] = m1.z; r[rr][8] = m1.w;
            if (x0 > 0) {
                float4 L = *(const float4*)(row + x0 - 4);
                r[rr][0] = L.w;
            } else r[rr][0] = 0.f;
            if (x0 + 8 < Wd) {
                float4 R = *(const float4*)(row + x0 + 8);
                r[rr][9] = R.x;
            } else r[rr][9] = 0.f;
        } else {
#pragma unroll
            for (int j = 0; j < 10; j++) r[rr][j] = 0.f;
        }
    }
    float bvv = bias[c];
    float a[8];
#pragma unroll
    for (int j = 0; j < 8; j++) a[j] = bvv;
#pragma unroll
    for (int rr = 0; rr < 3; rr++) {
#pragma unroll
        for (int dx = 0; dx < 3; dx++) {
            float wc = wv[rr*3 + dx];
#pragma unroll
            for (int j = 0; j < 8; j++)
                a[j] = fmaf(wc, r[rr][j+dx], a[j]);
        }
    }
    float* op = out + (size_t)bcimg*Hd*Wd + y*Wd + x0;
    float4 o0; o0.x=a[0]; o0.y=a[1]; o0.z=a[2]; o0.w=a[3];
    float4 o1; o1.x=a[4]; o1.y=a[5]; o1.z=a[6]; o1.w=a[7];
    *(float4*)(op)     = o0;
    *(float4*)(op + 4) = o1;
}

// ---------------- pointwise 1x1 conv: tf32 MMA + cp.async double buffer ----------------
// A (weights) smem: [128 oc][36 stride]; B smem: [32 k][136 stride]; 2 buffers.
#define AW 36
#define BW 136
#define ABUF (128*AW)            // 4608 floats
#define BBUF (32*BW)             // 4352 floats
#define PW_SMEM ((2*ABUF + 2*BBUF)*4)   // 71680 bytes
__global__ __launch_bounds__(256, 2) void pw_mma_k(
    const float* __restrict__ in, const float* __restrict__ wgt,
    const float* __restrict__ bias, float* __restrict__ out,
    int IC, int NP, int out_cstride, int out_coff) {
    extern __shared__ float S[];
    float* Af = S;               // 2 x ABUF
    float* Bf = S + 2*ABUF;      // 2 x BBUF
    uint32_t sbase = (uint32_t)__cvta_generic_to_shared(S);
    int b = blockIdx.z;
    int oc0 = blockIdx.y * 128;
    int p0 = blockIdx.x * 128;
    int tid = threadIdx.x;
    int lane = tid & 31, wid = tid >> 5;
    int wm = wid >> 2, wn = wid & 3;
    int g = lane >> 2, tig = lane & 3;
    const float* inb = in + (size_t)b * IC * NP;

    float4 acc[4][4];
#pragma unroll
    for (int i = 0; i < 4; i++)
#pragma unroll
        for (int j = 0; j < 4; j++) acc[i][j] = make_float4(0.f, 0.f, 0.f, 0.f);

    int a_oc = tid >> 1;
    int a_kb = (tid & 1) * 16;
    int b_kk = tid >> 3;
    int b_pb = (tid & 7) * 16;

    int NIT = IC >> 5;

    // stage tile (buf, k0)
    auto stage = [&](int buf, int k0) {
        const float* wr = wgt + (size_t)(oc0 + a_oc)*IC + k0 + a_kb;
        uint32_t adst = sbase + (buf*ABUF + a_oc*AW + a_kb)*4;
#pragma unroll
        for (int q = 0; q < 4; q++)
            cp16(adst + q*16, wr + q*4);
        const float* brow = inb + (size_t)(k0 + b_kk)*NP + p0 + b_pb;
        uint32_t bdst = sbase + (2*ABUF + buf*BBUF + b_kk*BW + b_pb)*4;
        int pg = p0 + b_pb;
#pragma unroll
        for (int q = 0; q < 4; q++) {
            int rem = (NP - (pg + q*4)) * 4;
            int nb = rem >= 16 ? 16 : (rem > 0 ? rem : 0);
            const float* src = brow + q*4;
            if (nb == 0) src = inb;       // safe dummy
            cp16z(bdst + q*16, src, nb);
        }
    };

    stage(0, 0);
    asm volatile("cp.async.commit_group;");

    for (int it = 0; it < NIT; it++) {
        int buf = it & 1;
        if (it + 1 < NIT) {
            stage(buf ^ 1, (it + 1) * 32);
            asm volatile("cp.async.commit_group;");
            asm volatile("cp.async.wait_group 1;");
        } else {
            asm volatile("cp.async.wait_group 0;");
        }
        __syncthreads();
        const float* Ab = Af + buf*ABUF;
        const float* Bb = Bf + buf*BBUF;
#pragma unroll
        for (int ks = 0; ks < 32; ks += 8) {
            uint32_t af[4][4];
#pragma unroll
            for (int mt = 0; mt < 4; mt++) {
                int oc = wm*64 + mt*16 + g;
                af[mt][0] = f2tf32(Ab[(oc  )*AW + ks + tig]);
                af[mt][1] = f2tf32(Ab[(oc+8)*AW + ks + tig]);
                af[mt][2] = f2tf32(Ab[(oc  )*AW + ks + tig + 4]);
                af[mt][3] = f2tf32(Ab[(oc+8)*AW + ks + tig + 4]);
            }
            uint32_t bf[4][2];
#pragma unroll
            for (int nt = 0; nt < 4; nt++) {
                int p = wn*32 + nt*8 + g;
                bf[nt][0] = f2tf32(Bb[(ks+tig  )*BW + p]);
                bf[nt][1] = f2tf32(Bb[(ks+tig+4)*BW + p]);
            }
#pragma unroll
            for (int mt = 0; mt < 4; mt++)
#pragma unroll
                for (int nt = 0; nt < 4; nt++)
                    mma_tf32(acc[mt][nt], af[mt][0], af[mt][1], af[mt][2], af[mt][3],
                             bf[nt][0], bf[nt][1]);
        }
        __syncthreads();
    }
    float* ob = out + (size_t)b * out_cstride * NP + (size_t)out_coff * NP;
#pragma unroll
    for (int mt = 0; mt < 4; mt++) {
        int r0 = oc0 + wm*64 + mt*16 + g;
        int r1 = r0 + 8;
        float bv0 = __ldg(bias + r0);
        float bv1 = __ldg(bias + r1);
        float* row0 = ob + (size_t)r0 * NP;
        float* row1 = ob + (size_t)r1 * NP;
#pragma unroll
        for (int nt = 0; nt < 4; nt++) {
            int c = p0 + wn*32 + nt*8 + tig*2;
            float4 a = acc[mt][nt];
            if (c + 1 < NP) {
                float2 v0; v0.x = a.x + bv0; v0.y = a.y + bv0;
                float2 v1; v1.x = a.z + bv1; v1.y = a.w + bv1;
                *(float2*)(row0 + c) = v0;
                *(float2*)(row1 + c) = v1;
            } else if (c < NP) {
                row0[c] = a.x + bv0;
                row1[c] = a.z + bv1;
            }
        }
    }
}

// ---------------- low-frequency global attention: flash tf32 MMA ----------------
#define LSM_WORDS 50432
__global__ __launch_bounds__(256) void lattn_mma_k(
    const float* __restrict__ q, const float* __restrict__ kv,
    float* __restrict__ o) {
    extern __shared__ uint32_t Su[];
    uint32_t* Ps = Su;                 // also Q staging (stride 36)
    uint32_t* Ks = Su + 8704;          // [32][584]
    uint32_t* Vs = Su + 27392;         // [576][40]
    int b = blockIdx.z, h = blockIdx.y;
    int p0 = blockIdx.x * 128;
    int tid = threadIdx.x;
    int lane = tid & 31, w = tid >> 5;
    int g = lane >> 2, tig = lane & 3;
    const float* qb  = q  + ((size_t)b*128 + h*32)*NP_FULL;
    const float* kvb = kv + ((size_t)b*256 + h*32)*GP;

    for (int i = tid; i < 128*32; i += 256) {
        int d = i >> 7, pix = i & 127;
        Ps[pix*36 + d] = f2tf32(qb[(size_t)d*NP_FULL + p0 + pix] * SCALE);
    }
    for (int i = tid; i < 576*32; i += 256) {
        int d = i / 576, kp = i - d*576;
        Ks[d*584 + kp] = f2tf32(kvb[(size_t)d*GP + kp]);
    }
    for (int i = tid; i < 576*32; i += 256) {
        int d = i / 576, kp = i - d*576;
        Vs[kp*40 + d] = f2tf32(kvb[(size_t)(128 + d)*GP + kp]);
    }
    __syncthreads();

    int r0 = w*16 + g;
    uint32_t aq[4][4];
#pragma unroll
    for (int kt = 0; kt < 4; kt++) {
        aq[kt][0] = Ps[(r0  )*36 + kt*8 + tig];
        aq[kt][1] = Ps[(r0+8)*36 + kt*8 + tig];
        aq[kt][2] = Ps[(r0  )*36 + kt*8 + tig + 4];
        aq[kt][3] = Ps[(r0+8)*36 + kt*8 + tig + 4];
    }
    __syncwarp();

    float4 oacc[4];
#pragma unroll
    for (int dt = 0; dt < 4; dt++) oacc[dt] = make_float4(0.f,0.f,0.f,0.f);
    float m0 = -1e30f, m1 = -1e30f, l0 = 0.f, l1 = 0.f;

    for (int c = 0; c < 9; c++) {
        int kb = c*64;
        float4 s[8];
#pragma unroll
        for (int nt = 0; nt < 8; nt++) s[nt] = make_float4(0.f,0.f,0.f,0.f);
#pragma unroll
        for (int kt = 0; kt < 4; kt++) {
#pragma unroll
            for (int nt = 0; nt < 8; nt++) {
                uint32_t b0 = Ks[(kt*8+tig  )*584 + kb + nt*8 + g];
                uint32_t b1 = Ks[(kt*8+tig+4)*584 + kb + nt*8 + g];
                mma_tf32(s[nt], aq[kt][0], aq[kt][1], aq[kt][2], aq[kt][3], b0, b1);
            }
        }
        float mx0 = -1e30f, mx1 = -1e30f;
#pragma unroll
        for (int nt = 0; nt < 8; nt++) {
            mx0 = fmaxf(mx0, fmaxf(s[nt].x, s[nt].y));
            mx1 = fmaxf(mx1, fmaxf(s[nt].z, s[nt].w));
        }
        mx0 = fmaxf(mx0, __shfl_xor_sync(0xffffffffu, mx0, 1));
        mx0 = fmaxf(mx0, __shfl_xor_sync(0xffffffffu, mx0, 2));
        mx1 = fmaxf(mx1, __shfl_xor_sync(0xffffffffu, mx1, 1));
        mx1 = fmaxf(mx1, __shfl_xor_sync(0xffffffffu, mx1, 2));
        float nm0 = fmaxf(m0, mx0), nm1 = fmaxf(m1, mx1);
        float al0 = __expf(m0 - nm0), al1 = __expf(m1 - nm1);
        m0 = nm0; m1 = nm1;
        float sum0 = 0.f, sum1 = 0.f;
#pragma unroll
        for (int nt = 0; nt < 8; nt++) {
            s[nt].x = __expf(s[nt].x - m0); sum0 += s[nt].x;
            s[nt].y = __expf(s[nt].y - m0); sum0 += s[nt].y;
            s[nt].z = __expf(s[nt].z - m1); sum1 += s[nt].z;
            s[nt].w = __expf(s[nt].w - m1); sum1 += s[nt].w;
        }
        l0 = l0*al0 + sum0;
        l1 = l1*al1 + sum1;
#pragma unroll
        for (int dt = 0; dt < 4; dt++) {
            oacc[dt].x *= al0; oacc[dt].y *= al0;
            oacc[dt].z *= al1; oacc[dt].w *= al1;
        }
        __syncwarp();
#pragma unroll
        for (int nt = 0; nt < 8; nt++) {
            uint2 u0; u0.x = f2tf32(s[nt].x); u0.y = f2tf32(s[nt].y);
            uint2 u1; u1.x = f2tf32(s[nt].z); u1.y = f2tf32(s[nt].w);
            *(uint2*)&Ps[(r0  )*68 + nt*8 + 2*tig] = u0;
            *(uint2*)&Ps[(r0+8)*68 + nt*8 + 2*tig] = u1;
        }
        __syncwarp();
#pragma unroll
        for (int kt2 = 0; kt2 < 8; kt2++) {
            uint32_t a0 = Ps[(r0  )*68 + kt2*8 + tig];
            uint32_t a1 = Ps[(r0+8)*68 + kt2*8 + tig];
            uint32_t a2 = Ps[(r0  )*68 + kt2*8 + tig + 4];
            uint32_t a3 = Ps[(r0+8)*68 + kt2*8 + tig + 4];
#pragma unroll
            for (int dt = 0; dt < 4; dt++) {
                uint32_t b0 = Vs[(kb + kt2*8 + tig  )*40 + dt*8 + g];
                uint32_t b1 = Vs[(kb + kt2*8 + tig+4)*40 + dt*8 + g];
                mma_tf32(oacc[dt], a0, a1, a2, a3, b0, b1);
            }
        }
    }
    l0 += __shfl_xor_sync(0xffffffffu, l0, 1);
    l0 += __shfl_xor_sync(0xffffffffu, l0, 2);
    l1 += __shfl_xor_sync(0xffffffffu, l1, 1);
    l1 += __shfl_xor_sync(0xffffffffu, l1, 2);
    float inv0 = 1.f / l0, inv1 = 1.f / l1;
    float* ob = o + ((size_t)b*128 + h*32)*NP_FULL + p0;
#pragma unroll
    for (int dt = 0; dt < 4; dt++) {
        int d0 = dt*8 + 2*tig;
        ob[(size_t)(d0  )*NP_FULL + r0    ] = oacc[dt].x * inv0;
        ob[(size_t)(d0+1)*NP_FULL + r0    ] = oacc[dt].y * inv0;
        ob[(size_t)(d0  )*NP_FULL + r0 + 8] = oacc[dt].z * inv1;
        ob[(size_t)(d0+1)*NP_FULL + r0 + 8] = oacc[dt].w * inv1;
    }
}

// ---------------- high-frequency windowed attention ----------------
__global__ __launch_bounds__(256) void hattn_k(
    const float* __restrict__ qkv, float* __restrict__ ho) {
    extern __shared__ float sm[];   // [384][64]
    int b = blockIdx.y;
    int g0 = blockIdx.x * 4;
    const float* qb = qkv + (size_t)b*384*NP_FULL;
    for (int i = threadIdx.x; i < 384*64; i += 256) {
        int c = i >> 6; int px = i & 63;
        int win = px >> 4, t = px & 15;
        int g = g0 + win; int gy = g / HGD, gx = g - gy*HGD;
        int pp = (gy*4 + (t >> 2))*WW_ + gx*4 + (t & 3);
        sm[i] = qb[(size_t)c*NP_FULL + pp];
    }
    __syncthreads();
    int tid = threadIdx.x;
    int t = tid & 15; int n = (tid >> 4) & 3; int win = tid >> 6;
    int pxb = win*16;
    float qv[32];
#pragma unroll
    for (int d = 0; d < 32; d++) qv[d] = sm[(n*32 + d)*64 + pxb + t];
    float sc[16];
    float mx = -1e30f;
#pragma unroll
    for (int k = 0; k < 16; k++) {
        float s = 0.f;
#pragma unroll
        for (int d = 0; d < 32; d++)
            s = fmaf(qv[d], sm[((4 + n)*32 + d)*64 + pxb + k], s);
        s *= SCALE;
        sc[k] = s;
        mx = fmaxf(mx, s);
    }
    float l = 0.f;
#pragma unroll
    for (int k = 0; k < 16; k++) { sc[k] = __expf(sc[k] - mx); l += sc[k]; }
    float inv = 1.f / l;
    int g = g0 + win; int gy = g / HGD, gx = g - gy*HGD;
    int pp = (gy*4 + (t >> 2))*WW_ + gx*4 + (t & 3);
    float* ob = ho + (size_t)b*128*NP_FULL + pp;
#pragma unroll
    for (int d = 0; d < 32; d++) {
        float s = 0.f;
#pragma unroll
        for (int k = 0; k < 16; k++)
            s = fmaf(sc[k], sm[((8 + n)*32 + d)*64 + pxb + k], s);
        ob[(size_t)(n*32 + d)*NP_FULL] = s * inv;
    }
}

// ---------------- launch ----------------
extern "C" void kernel_launch(void* const* d_in, const int* in_sizes, int n_in,
                              void* d_out, int out_size) {
    const float* x          = (const float*)d_in[0];
    const float* restore_w  = (const float*)d_in[1];
    const float* restore_b  = (const float*)d_in[2];
    const float* lq_dw_w    = (const float*)d_in[3];
    const float* lq_dw_b    = (const float*)d_in[4];
    const float* lq_pw_w    = (const float*)d_in[5];
    const float* lq_pw_b    = (const float*)d_in[6];
    const float* lkv_dw_w   = (const float*)d_in[7];
    const float* lkv_dw_b   = (const float*)d_in[8];
    const float* lkv_pw_w   = (const float*)d_in[9];
    const float* lkv_pw_b   = (const float*)d_in[10];
    const float* lproj_dw_w = (const float*)d_in[11];
    const float* lproj_dw_b = (const float*)d_in[12];
    const float* lproj_pw_w = (const float*)d_in[13];
    const float* lproj_pw_b = (const float*)d_in[14];
    const float* hqkv_dw_w  = (const float*)d_in[15];
    const float* hqkv_dw_b  = (const float*)d_in[16];
    const float* hqkv_pw_w  = (const float*)d_in[17];
    const float* hqkv_pw_b  = (const float*)d_in[18];
    const float* hproj_dw_w = (const float*)d_in[19];
    const float* hproj_dw_b = (const float*)d_in[20];
    const float* hproj_pw_w = (const float*)d_in[21];
    const float* hproj_pw_b = (const float*)d_in[22];
    float* out = (float*)d_out;

    float *low, *high, *dwA, *dwB, *lq, *lkvdw, *lkv, *lattn, *qkvb, *ho;
    cudaGetSymbolAddress((void**)&low,   g_low);
    cudaGetSymbolAddress((void**)&high,  g_high);
    cudaGetSymbolAddress((void**)&dwA,   g_dw);
    cudaGetSymbolAddress((void**)&dwB,   g_dw2);
    cudaGetSymbolAddress((void**)&lq,    g_lq);
    cudaGetSymbolAddress((void**)&lkvdw, g_lkvdw);
    cudaGetSymbolAddress((void**)&lkv,   g_lkv);
    cudaGetSymbolAddress((void**)&lattn, g_lattn);
    cudaGetSymbolAddress((void**)&qkvb,  g_qkv);
    cudaGetSymbolAddress((void**)&ho,    g_ho);

    static cudaStream_t s2 = nullptr;
    static cudaEvent_t evFork = nullptr, evJoin = nullptr;
    if (!s2) {
        cudaStreamCreateWithFlags(&s2, cudaStreamNonBlocking);
        cudaEventCreateWithFlags(&evFork, cudaEventDisableTiming);
        cudaEventCreateWithFlags(&evJoin, cudaEventDisableTiming);
        cudaFuncSetAttribute(pw_mma_k, cudaFuncAttributeMaxDynamicSharedMemorySize, PW_SMEM);
        cudaFuncSetAttribute(lattn_mma_k, cudaFuncAttributeMaxDynamicSharedMemorySize, LSM_WORDS*4);
        cudaFuncSetAttribute(hattn_k, cudaFuncAttributeMaxDynamicSharedMemorySize, 384*64*sizeof(float));
    }

    // ---- stream 0: pool (feeds both chains) ----
    {
        int total = BB*CC*GP;
        pool_k<<<(total + 255)/256, 256, 0>>>(x, low);
    }
    cudaEventRecord(evFork, 0);
    cudaStreamWaitEvent(s2, evFork, 0);

    // ======== HIGH chain on s2 ========
    high_k<<<dim3(NP_FULL/256, BB), 256, 0, s2>>>(x, low, restore_w, restore_b, high);
    {
        int total8 = BB*CC*NP_FULL/8;
        dw_k<<<(total8 + 255)/256, 256, 0, s2>>>(high, hqkv_dw_w, hqkv_dw_b, dwB, CC, HH_, WW_, total8);
    }
    pw_mma_k<<<dim3(NP_FULL/128, 3, BB), 256, PW_SMEM, s2>>>(dwB, hqkv_pw_w, hqkv_pw_b, qkvb, 256, NP_FULL, 384, 0);
    hattn_k<<<dim3(GP/4, BB), 256, 384*64*sizeof(float), s2>>>(qkvb, ho);
    {
        int total8 = BB*128*NP_FULL/8;
        dw_k<<<(total8 + 255)/256, 256, 0, s2>>>(ho, hproj_dw_w, hproj_dw_b, dwB, 128, HH_, WW_, total8);
    }
    pw_mma_k<<<dim3(NP_FULL/128, 1, BB), 256, PW_SMEM, s2>>>(dwB, hproj_pw_w, hproj_pw_b, out, 128, NP_FULL, 256, 128);
    cudaEventRecord(evJoin, s2);

    // ======== LOW chain on stream 0 ========
    {
        int total8 = BB*CC*NP_FULL/8;
        dw_k<<<(total8 + 255)/256, 256, 0>>>(x, lq_dw_w, lq_dw_b, dwA, CC, HH_, WW_, total8);
    }
    pw_mma_k<<<dim3(NP_FULL/128, 1, BB), 256, PW_SMEM>>>(dwA, lq_pw_w, lq_pw_b, lq, 256, NP_FULL, 128, 0);
    {
        int total8 = BB*CC*GP/8;
        dw_k<<<(total8 + 255)/256, 256, 0>>>(low, lkv_dw_w, lkv_dw_b, lkvdw, CC, HGD, HGD, total8);
    }
    pw_mma_k<<<dim3((GP + 127)/128, 2, BB), 256, PW_SMEM>>>(lkvdw, lkv_pw_w, lkv_pw_b, lkv, 256, GP, 256, 0);
    lattn_mma_k<<<dim3(NP_FULL/128, 4, BB), 256, LSM_WORDS*4>>>(lq, lkv, lattn);
    {
        int total8 = BB*128*NP_FULL/8;
        dw_k<<<(total8 + 255)/256, 256, 0>>>(lattn, lproj_dw_w, lproj_dw_b, dwA, 128, HH_, WW_, total8);
    }
    pw_mma_k<<<dim3(NP_FULL/128, 1, BB), 256, PW_SMEM>>>(dwA, lproj_pw_w, lproj_pw_b, out, 128, NP_FULL, 256, 0);

    // ---- join ----
    cudaStreamWaitEvent(0, evJoin, 0);
}